// round 4
// baseline (speedup 1.0000x reference)
#include <cuda_runtime.h>

typedef unsigned long long ull;

// Problem constants
constexpr int Bb = 64, Tt = 12, Nn = 1370, Cc = 8, Hh = 64;
constexpr int NSEQ   = Bb * Nn;     // 87680
constexpr int TILE   = 64;          // sequences per block
constexpr int THREADS = 512;        // 16 warps
constexpr int PAD    = 72;          // hx row: 64 h + 8 x floats (288B, 16B aligned)
static_assert((PAD * 4) % 16 == 0, "hx rows must be 16B aligned");

// Shared memory layout (float offsets)
constexpr int OFF_HX0 = 0;                       // [64][72] buffer 0
constexpr int OFF_HX1 = OFF_HX0 + TILE * PAD;    // [64][72] buffer 1
constexpr int OFF_C   = OFF_HX1 + TILE * PAD;    // [64][64] cell state
constexpr int OFF_WFC = OFF_C + TILE * Hh;       // [8][64]
constexpr int OFF_BFC = OFF_WFC + Cc * Hh;       // [8]
constexpr int SMEM_FLOATS = OFF_BFC + 8;
constexpr int SMEM_BYTES  = SMEM_FLOATS * 4;     // 55328 B

__device__ __forceinline__ void fma2(ull& acc, ull a, ull b) {
    // packed fp32x2 FMA: 2 fp32 FMAs per instruction (exact fp32 semantics per lane)
    asm("fma.rn.f32x2 %0, %1, %2, %0;" : "+l"(acc) : "l"(a), "l"(b));
}
__device__ __forceinline__ float hadd2(ull v) {
    float fx = __uint_as_float((unsigned)(v & 0xffffffffull));
    float fy = __uint_as_float((unsigned)(v >> 32));
    return fx + fy;
}
__device__ __forceinline__ float sigfast(float x) {
    return __fdividef(1.0f, 1.0f + __expf(-x));
}
__device__ __forceinline__ float tanhfast(float x) {
    return 1.0f - __fdividef(2.0f, 1.0f + __expf(2.0f * x));
}

__global__ void __launch_bounds__(THREADS, 1)
lstm_f32x2_kernel(const float* __restrict__ x,
                  const float* __restrict__ W_ih,
                  const float* __restrict__ W_hh,
                  const float* __restrict__ b_ih,
                  const float* __restrict__ b_hh,
                  const float* __restrict__ W_fc,
                  const float* __restrict__ b_fc,
                  float* __restrict__ out)
{
    extern __shared__ float sm[];
    float* sC   = sm + OFF_C;
    float* sWfc = sm + OFF_WFC;
    float* sBfc = sm + OFF_BFC;

    const int tid = threadIdx.x;

    // ---- Stage FC weights, zero h buffer 0 and cell state ----
    {
        const float4* g4 = reinterpret_cast<const float4*>(W_fc);
        float4*       s4 = reinterpret_cast<float4*>(sWfc);
        for (int i = tid; i < Cc * Hh / 4; i += THREADS) s4[i] = g4[i];
    }
    if (tid < Cc) sBfc[tid] = b_fc[tid];
    for (int i = tid; i < TILE * PAD; i += THREADS) sm[OFF_HX0 + i] = 0.0f;
    for (int i = tid; i < TILE * Hh;  i += THREADS) sC[i] = 0.0f;
    // (t=0 __syncthreads below orders these before first reads)

    // ---- Thread roles ----
    const int w    = tid >> 5;
    const int l    = tid & 31;
    const int sh   = w >> 3;          // seq-half: 0 -> seqs 0..31, 1 -> 32..63
    const int kc   = w & 7;           // k-chunk
    const int kk   = l & 7;
    const int gate = l >> 3;          // 0=i 1=f 2=g 3=o
    const int k    = kc * 8 + kk;
    const int row  = gate * 64 + k;   // row in (4H, *) weight matrices
    const int sbase = sh * 32;

    // ---- Register-resident weights: one gate row (W_hh[row] ++ W_ih[row]) ----
    ull wpack[36];
    {
        const float* whr = W_hh + row * Hh;
        #pragma unroll
        for (int j = 0; j < 32; j++)
            wpack[j] = *reinterpret_cast<const ull*>(whr + 2 * j);
        const float* wir = W_ih + row * Cc;
        #pragma unroll
        for (int j = 0; j < 4; j++)
            wpack[32 + j] = *reinterpret_cast<const ull*>(wir + 2 * j);
    }
    const float bias  = b_ih[row] + b_hh[row];
    const ull   bias2 = (ull)__float_as_uint(bias);   // pair (bias, 0)

    // activation = na * sigmoid(nb * pre) + nc  (gate g uses tanh = 2*sig(2x)-1)
    const float na = (gate == 2) ? 2.0f : 1.0f;
    const float nc = (gate == 2) ? -1.0f : 0.0f;

    // x loader mapping: one float per thread per step, coalesced
    const int ls  = tid >> 3, lc = tid & 7;
    const int lgs = blockIdx.x * TILE + ls;   // global seq = b*N + n
    const int lb  = lgs / Nn;
    const int ln  = lgs - lb * Nn;
    const int lx0 = ((lb * Tt) * Nn + ln) * Cc + lc;

    // ---- Time loop ----
    for (int t = 0; t < Tt; ++t) {
        float* rb = sm + ((t & 1) ? OFF_HX1 : OFF_HX0);  // read buffer (holds h_{t-1})
        float* wb = sm + ((t & 1) ? OFF_HX0 : OFF_HX1);  // write buffer (gets h_t)

        // load x_t into read buffer cols 64..71 (disjoint from h cols)
        rb[ls * PAD + 64 + lc] = x[lx0 + t * Nn * Cc];
        __syncthreads();   // h_{t-1} writes + x_t writes visible to all

        for (int si = 0; si < 32; ++si) {
            const int s = sbase + si;
            const double2* hx = reinterpret_cast<const double2*>(rb + s * PAD);

            ull a0 = bias2, a1 = 0ull;
            #pragma unroll
            for (int q = 0; q < 9; q++) {
                const double2 d = hx[q];                 // LDS.128 (uniform broadcast)
                fma2(a0, wpack[2 * q],     __double_as_longlong(d.x));
                fma2(a1, wpack[2 * q + 1], __double_as_longlong(d.y));
            }
            const double2 d9  = hx[9],  d10 = hx[10], d11 = hx[11];
            const double2 d12 = hx[12], d13 = hx[13], d14 = hx[14];
            const double2 d15 = hx[15], d16 = hx[16], d17 = hx[17];
            fma2(a0, wpack[18], __double_as_longlong(d9.x));  fma2(a1, wpack[19], __double_as_longlong(d9.y));
            fma2(a0, wpack[20], __double_as_longlong(d10.x)); fma2(a1, wpack[21], __double_as_longlong(d10.y));
            fma2(a0, wpack[22], __double_as_longlong(d11.x)); fma2(a1, wpack[23], __double_as_longlong(d11.y));
            fma2(a0, wpack[24], __double_as_longlong(d12.x)); fma2(a1, wpack[25], __double_as_longlong(d12.y));
            fma2(a0, wpack[26], __double_as_longlong(d13.x)); fma2(a1, wpack[27], __double_as_longlong(d13.y));
            fma2(a0, wpack[28], __double_as_longlong(d14.x)); fma2(a1, wpack[29], __double_as_longlong(d14.y));
            fma2(a0, wpack[30], __double_as_longlong(d15.x)); fma2(a1, wpack[31], __double_as_longlong(d15.y));
            fma2(a0, wpack[32], __double_as_longlong(d16.x)); fma2(a1, wpack[33], __double_as_longlong(d16.y));
            fma2(a0, wpack[34], __double_as_longlong(d17.x)); fma2(a1, wpack[35], __double_as_longlong(d17.y));

            const float pre = hadd2(a0) + hadd2(a1);
            const float act = fmaf(na, sigfast(na * pre), nc);  // na==nb

            // gather f,g,o into k-owner lanes (0..7); iv is local there
            const float fv = __shfl_sync(0xffffffffu, act, kk + 8);
            const float gv = __shfl_sync(0xffffffffu, act, kk + 16);
            const float ov = __shfl_sync(0xffffffffu, act, kk + 24);

            if (l < 8) {
                const float cold = sC[s * Hh + k];
                const float cnew = fmaf(fv, cold, act * gv);   // act == i here
                sC[s * Hh + k] = cnew;
                wb[s * PAD + k] = ov * tanhfast(cnew);
            }
        }
        // no 2nd barrier: next iter writes x into wb cols 64..71 (disjoint from
        // h cols 0..63) and its __syncthreads orders h_t writes before reads.
    }
    __syncthreads();   // final h (in buffer 0, since Tt even) visible

    // ---- FC epilogue: y[seq][c] = h . W_fc[c] + b_fc[c] ----
    {
        const int oc = tid & 7, os = tid >> 3;
        const float* hr = sm + OFF_HX0 + os * PAD;
        const float* wr = sWfc + oc * Hh;
        float acc = sBfc[oc];
        #pragma unroll 8
        for (int j = 0; j < Hh; j++) acc = fmaf(wr[j], hr[j], acc);
        out[(blockIdx.x * TILE + os) * Cc + oc] = acc;
    }
}

extern "C" void kernel_launch(void* const* d_in, const int* in_sizes, int n_in,
                              void* d_out, int out_size) {
    const float* x    = (const float*)d_in[0];
    const float* W_ih = (const float*)d_in[1];
    const float* W_hh = (const float*)d_in[2];
    const float* b_ih = (const float*)d_in[3];
    const float* b_hh = (const float*)d_in[4];
    const float* W_fc = (const float*)d_in[5];
    const float* b_fc = (const float*)d_in[6];
    float* out = (float*)d_out;

    cudaFuncSetAttribute(lstm_f32x2_kernel,
                         cudaFuncAttributeMaxDynamicSharedMemorySize, SMEM_BYTES);
    lstm_f32x2_kernel<<<NSEQ / TILE, THREADS, SMEM_BYTES>>>(
        x, W_ih, W_hh, b_ih, b_hh, W_fc, b_fc, out);
}

// round 5
// speedup vs baseline: 1.4225x; 1.4225x over previous
#include <cuda_runtime.h>

typedef unsigned long long ull;

// Problem constants
constexpr int Bb = 64, Tt = 12, Nn = 1370, Cc = 8, Hh = 64;
constexpr int NSEQ    = Bb * Nn;   // 87680
constexpr int TILE    = 128;       // sequences per block (87680/128 = 685 exact)
constexpr int THREADS = 512;       // 16 warps
constexpr int KP      = 72;        // packed row: 64 h + 8 x (floats)
constexpr int NPAIR   = 36;        // ull pairs per row
constexpr int G       = 256;       // gate rows

// Shared memory layout (float offsets). hT buffers are transposed: [pair][seq] as ull.
constexpr int OFF_T0   = 0;                         // ull[36][128] = 9216 floats
constexpr int OFF_T1   = OFF_T0 + NPAIR * TILE * 2; // 9216
constexpr int OFF_WP   = OFF_T1 + NPAIR * TILE * 2; // float[256][72] = 18432
constexpr int OFF_B    = OFF_WP + G * KP;           // [256]
constexpr int OFF_WFCP = OFF_B + G;                 // ull[8][32] = 512 floats
constexpr int OFF_BFC  = OFF_WFCP + 512;            // [8]
constexpr int SMEM_FLOATS = OFF_BFC + 8;
constexpr int SMEM_BYTES  = SMEM_FLOATS * 4;        // 150,560 B -> 1 CTA/SM

__device__ __forceinline__ void fma2(ull& acc, ull a, ull b) {
    asm("fma.rn.f32x2 %0, %1, %2, %0;" : "+l"(acc) : "l"(a), "l"(b));
}
__device__ __forceinline__ float hadd2(ull v) {
    return __uint_as_float((unsigned)(v & 0xffffffffull)) +
           __uint_as_float((unsigned)(v >> 32));
}
__device__ __forceinline__ ull bias2(float b) {        // pair (b, 0)
    return (ull)__float_as_uint(b);
}
__device__ __forceinline__ ull packf2(float lo, float hi) {
    return (ull)__float_as_uint(lo) | ((ull)__float_as_uint(hi) << 32);
}
__device__ __forceinline__ float sigf(float x) {
    return __fdividef(1.0f, 1.0f + __expf(-x));
}
__device__ __forceinline__ float tanhfast(float x) {
    return 1.0f - __fdividef(2.0f, 1.0f + __expf(2.0f * x));
}

// One GEMM pass over two gate-row groups (rb0, rb1), 8 rows each, 2 seqs per lane.
// acc[g][r][ss] — f32x2 partial sums (even j, odd j).
__device__ __forceinline__ void lstm_pass(const float* __restrict__ sWp,
                                          const ull*   __restrict__ rbT,
                                          const float* __restrict__ sB,
                                          int rb0, int rb1, int kc, int s1, int s2,
                                          ull acc[2][8][2])
{
    const int r0 = rb0 + kc * 8, r1 = rb1 + kc * 8;
    #pragma unroll
    for (int r = 0; r < 8; r++) {
        acc[0][r][0] = bias2(sB[r0 + r]); acc[0][r][1] = acc[0][r][0];
        acc[1][r][0] = bias2(sB[r1 + r]); acc[1][r][1] = acc[1][r][0];
    }
    const float* w0b = sWp + r0 * KP;
    const float* w1b = sWp + r1 * KP;
    #pragma unroll 2
    for (int q = 0; q < 18; q++) {
        const ull h0a = rbT[(2 * q)     * TILE + s1];
        const ull h1a = rbT[(2 * q + 1) * TILE + s1];
        const ull h0b = rbT[(2 * q)     * TILE + s2];
        const ull h1b = rbT[(2 * q + 1) * TILE + s2];
        #pragma unroll
        for (int r = 0; r < 8; r++) {
            const double2 wa = *reinterpret_cast<const double2*>(w0b + r * KP + 4 * q);
            const ull wa0 = __double_as_longlong(wa.x), wa1 = __double_as_longlong(wa.y);
            fma2(acc[0][r][0], wa0, h0a); fma2(acc[0][r][0], wa1, h1a);
            fma2(acc[0][r][1], wa0, h0b); fma2(acc[0][r][1], wa1, h1b);
            const double2 wb = *reinterpret_cast<const double2*>(w1b + r * KP + 4 * q);
            const ull wb0 = __double_as_longlong(wb.x), wb1 = __double_as_longlong(wb.y);
            fma2(acc[1][r][0], wb0, h0a); fma2(acc[1][r][0], wb1, h1a);
            fma2(acc[1][r][1], wb0, h0b); fma2(acc[1][r][1], wb1, h1b);
        }
    }
}

__global__ void __launch_bounds__(THREADS, 1)
lstm_2s_kernel(const float* __restrict__ x,
               const float* __restrict__ W_ih,
               const float* __restrict__ W_hh,
               const float* __restrict__ b_ih,
               const float* __restrict__ b_hh,
               const float* __restrict__ W_fc,
               const float* __restrict__ b_fc,
               float* __restrict__ out)
{
    extern __shared__ __align__(16) float sm[];
    ull*   T0    = reinterpret_cast<ull*>(sm + OFF_T0);
    ull*   T1    = reinterpret_cast<ull*>(sm + OFF_T1);
    float* sWp   = sm + OFF_WP;
    float* sB    = sm + OFF_B;
    ull*   sWfcP = reinterpret_cast<ull*>(sm + OFF_WFCP);
    float* sBfc  = sm + OFF_BFC;

    const int tid = threadIdx.x;

    // ---- Stage: packed weights W_hh|W_ih per gate row ----
    for (int i = tid; i < G * KP; i += THREADS) {
        const int row = i / KP, j = i - row * KP;
        sWp[i] = (j < Hh) ? W_hh[row * Hh + j] : W_ih[row * Cc + (j - Hh)];
    }
    for (int i = tid; i < G; i += THREADS) sB[i] = b_ih[i] + b_hh[i];
    for (int i = tid; i < 256; i += THREADS) {         // FC weight pairs [8][32]
        const int oc = i >> 5, p = i & 31;
        sWfcP[i] = packf2(W_fc[oc * Hh + 2 * p], W_fc[oc * Hh + 2 * p + 1]);
    }
    if (tid < Cc) sBfc[tid] = b_fc[tid];
    for (int i = tid; i < NPAIR * TILE; i += THREADS) T0[i] = 0ull;  // h0 = 0

    // ---- Thread roles ----
    const int w  = tid >> 5;
    const int l  = tid & 31;
    const int sg = w >> 3;            // seq group: 0 -> 0..63, 1 -> 64..127
    const int kc = w & 7;             // k-chunk (8 k's)
    const int s1 = sg * 64 + l;
    const int s2 = s1 + 32;

    // x loader: thread loads float2 (2 consecutive channels) per step
    const int ls  = tid >> 2;                   // seq 0..127
    const int lc  = (2 * tid) & 7;              // channel 0,2,4,6
    const int lgs = blockIdx.x * TILE + ls;
    const int lb  = lgs / Nn;
    const int ln  = lgs - lb * Nn;
    const long lx0 = ((long)(lb * Tt) * Nn + ln) * Cc + lc;
    const int xslot = (32 + (lc >> 1)) * TILE + ls;

    float c1[8], c2[8];
    #pragma unroll
    for (int r = 0; r < 8; r++) { c1[r] = 0.0f; c2[r] = 0.0f; }

    #pragma unroll 1
    for (int t = 0; t < Tt; ++t) {
        ull* rbT = (t & 1) ? T1 : T0;
        ull* wbT = (t & 1) ? T0 : T1;

        // load x_t into read buffer (pairs 32..35; disjoint from h pairs 0..31)
        {
            const float2 xv = *reinterpret_cast<const float2*>(x + lx0 + (long)t * Nn * Cc);
            rbT[xslot] = packf2(xv.x, xv.y);
        }
        __syncthreads();   // h_{t-1} + x_t visible

        ull acc[2][8][2];

        // pass A: gates i (rows 0..63) and g (rows 128..191)
        lstm_pass(sWp, rbT, sB, 0, 128, kc, s1, s2, acc);
        float ig1[8], ig2[8];
        #pragma unroll
        for (int r = 0; r < 8; r++) {
            ig1[r] = sigf(hadd2(acc[0][r][0])) * tanhfast(hadd2(acc[1][r][0]));
            ig2[r] = sigf(hadd2(acc[0][r][1])) * tanhfast(hadd2(acc[1][r][1]));
        }

        // pass B: gates f (rows 64..127) and o (rows 192..255)
        lstm_pass(sWp, rbT, sB, 64, 192, kc, s1, s2, acc);
        float* wf = reinterpret_cast<float*>(wbT);
        #pragma unroll
        for (int r = 0; r < 8; r++) {
            const int k = kc * 8 + r;
            const float f1 = sigf(hadd2(acc[0][r][0]));
            const float o1 = sigf(hadd2(acc[1][r][0]));
            c1[r] = fmaf(f1, c1[r], ig1[r]);
            wf[((k >> 1) * TILE + s1) * 2 + (k & 1)] = o1 * tanhfast(c1[r]);
            const float f2 = sigf(hadd2(acc[0][r][1]));
            const float o2 = sigf(hadd2(acc[1][r][1]));
            c2[r] = fmaf(f2, c2[r], ig2[r]);
            wf[((k >> 1) * TILE + s2) * 2 + (k & 1)] = o2 * tanhfast(c2[r]);
        }
        // next iteration's __syncthreads orders these h writes before reads
    }
    __syncthreads();   // Tt even -> final h lives in T0

    // ---- FC epilogue: each thread produces 2 outputs (same seq, channels oc, oc+1) ----
    {
        const int os  = tid >> 2;
        const int oc0 = (2 * tid) & 7;
        ull a0 = 0ull, a1 = 0ull;
        #pragma unroll 4
        for (int p = 0; p < 32; p++) {
            const ull hp = T0[p * TILE + os];
            fma2(a0, sWfcP[oc0 * 32 + p],       hp);
            fma2(a1, sWfcP[(oc0 + 1) * 32 + p], hp);
        }
        const float y0 = hadd2(a0) + sBfc[oc0];
        const float y1 = hadd2(a1) + sBfc[oc0 + 1];
        *reinterpret_cast<float2*>(out + ((long)blockIdx.x * TILE + os) * Cc + oc0)
            = make_float2(y0, y1);
    }
}

extern "C" void kernel_launch(void* const* d_in, const int* in_sizes, int n_in,
                              void* d_out, int out_size) {
    const float* x    = (const float*)d_in[0];
    const float* W_ih = (const float*)d_in[1];
    const float* W_hh = (const float*)d_in[2];
    const float* b_ih = (const float*)d_in[3];
    const float* b_hh = (const float*)d_in[4];
    const float* W_fc = (const float*)d_in[5];
    const float* b_fc = (const float*)d_in[6];
    float* out = (float*)d_out;

    cudaFuncSetAttribute(lstm_2s_kernel,
                         cudaFuncAttributeMaxDynamicSharedMemorySize, SMEM_BYTES);
    lstm_2s_kernel<<<NSEQ / TILE, THREADS, SMEM_BYTES>>>(
        x, W_ih, W_hh, b_ih, b_hh, W_fc, b_fc, out);
}

// round 6
// speedup vs baseline: 1.4274x; 1.0034x over previous
#include <cuda_runtime.h>

typedef unsigned long long ull;

// Problem constants
constexpr int Bb = 64, Tt = 12, Nn = 1370, Cc = 8, Hh = 64;
constexpr int NSEQ    = Bb * Nn;   // 87680
constexpr int TILE    = 128;       // sequences per block (87680/128 = 685 exact)
constexpr int THREADS = 512;       // 16 warps
constexpr int KP      = 72;        // packed row: 64 h + 8 x (floats)
constexpr int NPAIR   = 36;        // ull pairs per row
constexpr int G       = 256;       // gate rows

// Shared memory layout (float offsets). hT buffers are transposed: [pair][seq] as ull.
constexpr int OFF_T0   = 0;                         // ull[36][128] = 9216 floats
constexpr int OFF_T1   = OFF_T0 + NPAIR * TILE * 2; // 9216
constexpr int OFF_WP   = OFF_T1 + NPAIR * TILE * 2; // float[256][72] = 18432
constexpr int OFF_B    = OFF_WP + G * KP;           // [256]
constexpr int OFF_WFCP = OFF_B + G;                 // ull[8][32] = 512 floats
constexpr int OFF_BFC  = OFF_WFCP + 512;            // [8]
constexpr int SMEM_FLOATS = OFF_BFC + 8;
constexpr int SMEM_BYTES  = SMEM_FLOATS * 4;        // 150,560 B -> 1 CTA/SM

__device__ __forceinline__ void fma2(ull& acc, ull a, ull b) {
    asm("fma.rn.f32x2 %0, %1, %2, %0;" : "+l"(acc) : "l"(a), "l"(b));
}
__device__ __forceinline__ float hadd2(ull v) {
    return __uint_as_float((unsigned)(v & 0xffffffffull)) +
           __uint_as_float((unsigned)(v >> 32));
}
__device__ __forceinline__ ull bias2(float b) {        // pair (b, 0)
    return (ull)__float_as_uint(b);
}
__device__ __forceinline__ ull packf2(float lo, float hi) {
    return (ull)__float_as_uint(lo) | ((ull)__float_as_uint(hi) << 32);
}
__device__ __forceinline__ float sigf(float x) {
    return __fdividef(1.0f, 1.0f + __expf(-x));
}
__device__ __forceinline__ float tanhfast(float x) {
    return 1.0f - __fdividef(2.0f, 1.0f + __expf(2.0f * x));
}

// One GEMM pass over two gate-row groups (rb0, rb1), 8 rows each, 2 seqs per lane.
// acc[g][r][ss] — f32x2 partial sums (even j, odd j).
__device__ __forceinline__ void lstm_pass(const float* __restrict__ sWp,
                                          const ull*   __restrict__ rbT,
                                          const float* __restrict__ sB,
                                          int rb0, int rb1, int kc, int s1, int s2,
                                          ull acc[2][8][2])
{
    const int r0 = rb0 + kc * 8, r1 = rb1 + kc * 8;
    #pragma unroll
    for (int r = 0; r < 8; r++) {
        acc[0][r][0] = bias2(sB[r0 + r]); acc[0][r][1] = acc[0][r][0];
        acc[1][r][0] = bias2(sB[r1 + r]); acc[1][r][1] = acc[1][r][0];
    }
    const float* w0b = sWp + r0 * KP;
    const float* w1b = sWp + r1 * KP;
    #pragma unroll 2
    for (int q = 0; q < 18; q++) {
        const ull h0a = rbT[(2 * q)     * TILE + s1];
        const ull h1a = rbT[(2 * q + 1) * TILE + s1];
        const ull h0b = rbT[(2 * q)     * TILE + s2];
        const ull h1b = rbT[(2 * q + 1) * TILE + s2];
        #pragma unroll
        for (int r = 0; r < 8; r++) {
            const double2 wa = *reinterpret_cast<const double2*>(w0b + r * KP + 4 * q);
            const ull wa0 = __double_as_longlong(wa.x), wa1 = __double_as_longlong(wa.y);
            fma2(acc[0][r][0], wa0, h0a); fma2(acc[0][r][0], wa1, h1a);
            fma2(acc[0][r][1], wa0, h0b); fma2(acc[0][r][1], wa1, h1b);
            const double2 wb = *reinterpret_cast<const double2*>(w1b + r * KP + 4 * q);
            const ull wb0 = __double_as_longlong(wb.x), wb1 = __double_as_longlong(wb.y);
            fma2(acc[1][r][0], wb0, h0a); fma2(acc[1][r][0], wb1, h1a);
            fma2(acc[1][r][1], wb0, h0b); fma2(acc[1][r][1], wb1, h1b);
        }
    }
}

__global__ void __launch_bounds__(THREADS, 1)
lstm_2s_kernel(const float* __restrict__ x,
               const float* __restrict__ W_ih,
               const float* __restrict__ W_hh,
               const float* __restrict__ b_ih,
               const float* __restrict__ b_hh,
               const float* __restrict__ W_fc,
               const float* __restrict__ b_fc,
               float* __restrict__ out)
{
    extern __shared__ __align__(16) float sm[];
    ull*   T0    = reinterpret_cast<ull*>(sm + OFF_T0);
    ull*   T1    = reinterpret_cast<ull*>(sm + OFF_T1);
    float* sWp   = sm + OFF_WP;
    float* sB    = sm + OFF_B;
    ull*   sWfcP = reinterpret_cast<ull*>(sm + OFF_WFCP);
    float* sBfc  = sm + OFF_BFC;

    const int tid = threadIdx.x;

    // ---- Stage: packed weights W_hh|W_ih per gate row ----
    for (int i = tid; i < G * KP; i += THREADS) {
        const int row = i / KP, j = i - row * KP;
        sWp[i] = (j < Hh) ? W_hh[row * Hh + j] : W_ih[row * Cc + (j - Hh)];
    }
    for (int i = tid; i < G; i += THREADS) sB[i] = b_ih[i] + b_hh[i];
    for (int i = tid; i < 256; i += THREADS) {         // FC weight pairs [8][32]
        const int oc = i >> 5, p = i & 31;
        sWfcP[i] = packf2(W_fc[oc * Hh + 2 * p], W_fc[oc * Hh + 2 * p + 1]);
    }
    if (tid < Cc) sBfc[tid] = b_fc[tid];
    for (int i = tid; i < NPAIR * TILE; i += THREADS) T0[i] = 0ull;  // h0 = 0

    // ---- Thread roles ----
    const int w  = tid >> 5;
    const int l  = tid & 31;
    const int sg = w >> 3;            // seq group: 0 -> 0..63, 1 -> 64..127
    const int kc = w & 7;             // k-chunk (8 k's)
    const int s1 = sg * 64 + l;
    const int s2 = s1 + 32;

    // x loader: thread loads float2 (2 consecutive channels) per step
    const int ls  = tid >> 2;                   // seq 0..127
    const int lc  = (2 * tid) & 7;              // channel 0,2,4,6
    const int lgs = blockIdx.x * TILE + ls;
    const int lb  = lgs / Nn;
    const int ln  = lgs - lb * Nn;
    const long lx0 = ((long)(lb * Tt) * Nn + ln) * Cc + lc;
    const int xslot = (32 + (lc >> 1)) * TILE + ls;

    float c1[8], c2[8];
    #pragma unroll
    for (int r = 0; r < 8; r++) { c1[r] = 0.0f; c2[r] = 0.0f; }

    #pragma unroll 1
    for (int t = 0; t < Tt; ++t) {
        ull* rbT = (t & 1) ? T1 : T0;
        ull* wbT = (t & 1) ? T0 : T1;

        // load x_t into read buffer (pairs 32..35; disjoint from h pairs 0..31)
        {
            const float2 xv = *reinterpret_cast<const float2*>(x + lx0 + (long)t * Nn * Cc);
            rbT[xslot] = packf2(xv.x, xv.y);
        }
        __syncthreads();   // h_{t-1} + x_t visible

        ull acc[2][8][2];

        // pass A: gates i (rows 0..63) and g (rows 128..191)
        lstm_pass(sWp, rbT, sB, 0, 128, kc, s1, s2, acc);
        float ig1[8], ig2[8];
        #pragma unroll
        for (int r = 0; r < 8; r++) {
            ig1[r] = sigf(hadd2(acc[0][r][0])) * tanhfast(hadd2(acc[1][r][0]));
            ig2[r] = sigf(hadd2(acc[0][r][1])) * tanhfast(hadd2(acc[1][r][1]));
        }

        // pass B: gates f (rows 64..127) and o (rows 192..255)
        lstm_pass(sWp, rbT, sB, 64, 192, kc, s1, s2, acc);
        float* wf = reinterpret_cast<float*>(wbT);
        #pragma unroll
        for (int r = 0; r < 8; r++) {
            const int k = kc * 8 + r;
            const float f1 = sigf(hadd2(acc[0][r][0]));
            const float o1 = sigf(hadd2(acc[1][r][0]));
            c1[r] = fmaf(f1, c1[r], ig1[r]);
            wf[((k >> 1) * TILE + s1) * 2 + (k & 1)] = o1 * tanhfast(c1[r]);
            const float f2 = sigf(hadd2(acc[0][r][1]));
            const float o2 = sigf(hadd2(acc[1][r][1]));
            c2[r] = fmaf(f2, c2[r], ig2[r]);
            wf[((k >> 1) * TILE + s2) * 2 + (k & 1)] = o2 * tanhfast(c2[r]);
        }
        // next iteration's __syncthreads orders these h writes before reads
    }
    __syncthreads();   // Tt even -> final h lives in T0

    // ---- FC epilogue: each thread produces 2 outputs (same seq, channels oc, oc+1) ----
    {
        const int os  = tid >> 2;
        const int oc0 = (2 * tid) & 7;
        ull a0 = 0ull, a1 = 0ull;
        #pragma unroll 4
        for (int p = 0; p < 32; p++) {
            const ull hp = T0[p * TILE + os];
            fma2(a0, sWfcP[oc0 * 32 + p],       hp);
            fma2(a1, sWfcP[(oc0 + 1) * 32 + p], hp);
        }
        const float y0 = hadd2(a0) + sBfc[oc0];
        const float y1 = hadd2(a1) + sBfc[oc0 + 1];
        *reinterpret_cast<float2*>(out + ((long)blockIdx.x * TILE + os) * Cc + oc0)
            = make_float2(y0, y1);
    }
}

extern "C" void kernel_launch(void* const* d_in, const int* in_sizes, int n_in,
                              void* d_out, int out_size) {
    const float* x    = (const float*)d_in[0];
    const float* W_ih = (const float*)d_in[1];
    const float* W_hh = (const float*)d_in[2];
    const float* b_ih = (const float*)d_in[3];
    const float* b_hh = (const float*)d_in[4];
    const float* W_fc = (const float*)d_in[5];
    const float* b_fc = (const float*)d_in[6];
    float* out = (float*)d_out;

    cudaFuncSetAttribute(lstm_2s_kernel,
                         cudaFuncAttributeMaxDynamicSharedMemorySize, SMEM_BYTES);
    lstm_2s_kernel<<<NSEQ / TILE, THREADS, SMEM_BYTES>>>(
        x, W_ih, W_hh, b_ih, b_hh, W_fc, b_fc, out);
}

// round 9
// speedup vs baseline: 3.8642x; 2.7073x over previous
#include <cuda_runtime.h>
#include <cuda_bf16.h>
#include <cstdint>

typedef uint32_t u32; typedef uint16_t u16;

// Problem constants
constexpr int Tt = 12, Nn = 1370;
constexpr int TILE = 128, THREADS = 256;           // 8 warps
constexpr int GRID = 87680 / TILE;                 // 685

// SMEM layout (bytes). Row stride 176B (88 bf16) -> conflict-free ldmatrix.
constexpr u32 SROW    = 176;
constexpr u32 OFF_WH  = 0;                         // W staging hi [256 rows][88] bf16 (init only)
constexpr u32 OFF_WL  = 45056;                     // W staging lo
constexpr u32 OFF_HH  = 0;                         // hx hi [128][88] bf16 (reuses WH region)
constexpr u32 OFF_HL  = 22528;                     // hx lo
constexpr u32 OFF_WFC = 90112;                     // float[8][64]
constexpr u32 OFF_BFC = OFF_WFC + 2048;            // float[8]
constexpr u32 SMEM_BYTES = OFF_BFC + 32;           // 92176

__device__ __forceinline__ float tanh_ap(float x) {
    float r; asm("tanh.approx.f32 %0, %1;" : "=f"(r) : "f"(x)); return r;
}
__device__ __forceinline__ float sig_ap(float x) {         // sigmoid via tanh (1 MUFU)
    return fmaf(0.5f, tanh_ap(0.5f * x), 0.5f);
}
__device__ __forceinline__ float tanh_pr(float x) {        // precise-ish tanh for output path
    return 1.0f - __fdividef(2.0f, 1.0f + __expf(2.0f * x));
}
__device__ __forceinline__ u16 bfh(float v) {
    return __bfloat16_as_ushort(__float2bfloat16(v));
}
__device__ __forceinline__ float bff(u16 b) {
    return __bfloat162float(__ushort_as_bfloat16(b));
}

__device__ __forceinline__ void ldmx4(u32* r, u32 addr) {
    asm volatile("ldmatrix.sync.aligned.m8n8.x4.shared.b16 {%0,%1,%2,%3}, [%4];"
        : "=r"(r[0]), "=r"(r[1]), "=r"(r[2]), "=r"(r[3]) : "r"(addr));
}
__device__ __forceinline__ void ldmx2(u32* r, u32 addr) {
    asm volatile("ldmatrix.sync.aligned.m8n8.x2.shared.b16 {%0,%1}, [%2];"
        : "=r"(r[0]), "=r"(r[1]) : "r"(addr));
}
__device__ __forceinline__ void mma16(float* d, const u32* a, u32 b0, u32 b1) {
    asm volatile("mma.sync.aligned.m16n8k16.row.col.f32.bf16.bf16.f32 "
        "{%0,%1,%2,%3}, {%4,%5,%6,%7}, {%8,%9}, {%0,%1,%2,%3};"
        : "+f"(d[0]), "+f"(d[1]), "+f"(d[2]), "+f"(d[3])
        : "r"(a[0]), "r"(a[1]), "r"(a[2]), "r"(a[3]), "r"(b0), "r"(b1));
}
__device__ __forceinline__ void mma8(float* d, const u32* a, u32 b0) {
    asm volatile("mma.sync.aligned.m16n8k8.row.col.f32.bf16.bf16.f32 "
        "{%0,%1,%2,%3}, {%4,%5}, {%6}, {%0,%1,%2,%3};"
        : "+f"(d[0]), "+f"(d[1]), "+f"(d[2]), "+f"(d[3])
        : "r"(a[0]), "r"(a[1]), "r"(b0));
}

__global__ void __launch_bounds__(THREADS, 1)
lstm_mma_kernel(const float* __restrict__ x,
                const float* __restrict__ W_ih,
                const float* __restrict__ W_hh,
                const float* __restrict__ b_ih,
                const float* __restrict__ b_hh,
                const float* __restrict__ W_fc,
                const float* __restrict__ b_fc,
                float* __restrict__ out)
{
    extern __shared__ __align__(16) char smc[];
    const u32 sb = (u32)__cvta_generic_to_shared(smc);

    const int tid = threadIdx.x;
    const int w = tid >> 5, l = tid & 31;
    const int grp = l >> 3, lr = l & 7;
    const int kml = (w << 3) + (l >> 2);    // lane's hidden index k (0..63)

    float* sWfc = (float*)(smc + OFF_WFC);
    float* sBfc = (float*)(smc + OFF_BFC);

    // ---- Stage W (hi/lo bf16) in permuted gate-row order ----
    // permuted row p = 32w + 16*tau + tr:
    //   tau=0: tr<8 -> i_{8w+tr}, tr>=8 -> g_{8w+tr-8}
    //   tau=1: tr<8 -> f_{8w+tr}, tr>=8 -> o_{8w+tr-8}
    for (int idx = tid; idx < 256 * 72; idx += THREADS) {
        const int p = idx / 72, col = idx % 72;
        const int pw = p >> 5, tau = (p >> 4) & 1, tr = p & 15;
        const int gate = tau ? ((tr < 8) ? 1 : 3) : ((tr < 8) ? 0 : 2);
        const int orig = (gate << 6) + (pw << 3) + (tr & 7);
        const float v = (col < 64) ? W_hh[orig * 64 + col] : W_ih[orig * 8 + (col - 64)];
        const u16 hi = bfh(v);
        *(u16*)(smc + OFF_WH + p * SROW + col * 2) = hi;
        *(u16*)(smc + OFF_WL + p * SROW + col * 2) = bfh(v - bff(hi));
    }
    for (int i = tid; i < 512; i += THREADS) sWfc[i] = W_fc[i];
    if (tid < 8) sBfc[tid] = b_fc[tid];

    // biases for this lane's k (all 4 gates)
    const float bi = b_ih[kml]       + b_hh[kml];
    const float bf = b_ih[64 + kml]  + b_hh[64 + kml];
    const float bg = b_ih[128 + kml] + b_hh[128 + kml];
    const float bo = b_ih[192 + kml] + b_hh[192 + kml];

    __syncthreads();

    // ---- Build static A (weight) fragments in registers ----
    u32 Ah[2][4][4], Al[2][4][4], Ah8[2][2], Al8[2][2];
    const u32 laneA  = (u32)(((grp & 1) * 8 + lr) * SROW + (grp >> 1) * 16);
    const u32 laneA8 = (u32)((((l >> 3) & 1) * 8 + lr) * SROW + 128);
    #pragma unroll
    for (int tau = 0; tau < 2; tau++) {
        const u32 pr = (u32)(w * 32 + tau * 16) * SROW;
        #pragma unroll
        for (int kc = 0; kc < 4; kc++) {
            ldmx4(Ah[tau][kc], sb + OFF_WH + pr + laneA + kc * 32);
            ldmx4(Al[tau][kc], sb + OFF_WL + pr + laneA + kc * 32);
        }
        ldmx2(Ah8[tau], sb + OFF_WH + pr + laneA8);
        ldmx2(Al8[tau], sb + OFF_WL + pr + laneA8);
    }
    __syncthreads();   // done reading W staging; region becomes hx

    // ---- Zero h columns (0..63) of both hx planes ----
    for (int i = tid; i < 128 * 32; i += THREADS) {
        const int row = i >> 5, cp = i & 31;
        *(u32*)(smc + OFF_HH + row * SROW + cp * 4) = 0u;
        *(u32*)(smc + OFF_HL + row * SROW + cp * 4) = 0u;
    }

    // ---- x loader mapping: thread -> (seq = tid/2, channel-half) ----
    const int fs = tid >> 1, half = tid & 1;
    const int gseq = blockIdx.x * TILE + fs;
    const int xb = gseq / Nn, xn = gseq - xb * Nn;
    const float* xp = x + ((size_t)(xb * Tt) * Nn + xn) * 8 + half * 4;
    const u32 xdst = (u32)(fs * SROW + 128 + half * 8);
    {   // x_0
        const float4 v = *(const float4*)xp;
        const u16 h0 = bfh(v.x), h1 = bfh(v.y), h2 = bfh(v.z), h3 = bfh(v.w);
        *(u32*)(smc + OFF_HH + xdst)     = (u32)h0 | ((u32)h1 << 16);
        *(u32*)(smc + OFF_HH + xdst + 4) = (u32)h2 | ((u32)h3 << 16);
        *(u32*)(smc + OFF_HL + xdst)     = (u32)bfh(v.x - bff(h0)) | ((u32)bfh(v.y - bff(h1)) << 16);
        *(u32*)(smc + OFF_HL + xdst + 4) = (u32)bfh(v.z - bff(h2)) | ((u32)bfh(v.w - bff(h3)) << 16);
        xp += Nn * 8;
    }
    __syncthreads();

    // B-operand lane address pieces
    const u32 laneB  = (u32)(((grp >> 1) * 8 + lr) * SROW + (grp & 1) * 16);
    const u32 laneB8 = (u32)((grp * 8 + lr) * SROW + 128);

    float cst[32], hst[32];
    #pragma unroll
    for (int i = 0; i < 32; i++) cst[i] = 0.0f;

    // =================== time loop ===================
    #pragma unroll 1
    for (int t = 0; t < Tt; ++t) {
        #pragma unroll
        for (int q = 0; q < 4; q++) {               // 4 seq-quarters (4 n-tiles each)
            float D[2][4][4];
            #pragma unroll
            for (int a = 0; a < 2; a++)
                #pragma unroll
                for (int n = 0; n < 4; n++)
                    #pragma unroll
                    for (int r = 0; r < 4; r++) D[a][n][r] = 0.0f;

            #pragma unroll
            for (int kc = 0; kc < 4; kc++) {
                #pragma unroll
                for (int np = 0; np < 2; np++) {
                    const u32 nb = (u32)((q * 4 + np * 2) * 8) * SROW + laneB + (u32)kc * 32;
                    u32 Bh[4], Bl[4];
                    ldmx4(Bh, sb + OFF_HH + nb);
                    ldmx4(Bl, sb + OFF_HL + nb);
                    #pragma unroll
                    for (int tau = 0; tau < 2; tau++) {
                        mma16(D[tau][np * 2],     Ah[tau][kc], Bh[0], Bh[1]);
                        mma16(D[tau][np * 2],     Al[tau][kc], Bh[0], Bh[1]);
                        mma16(D[tau][np * 2],     Ah[tau][kc], Bl[0], Bl[1]);
                        mma16(D[tau][np * 2 + 1], Ah[tau][kc], Bh[2], Bh[3]);
                        mma16(D[tau][np * 2 + 1], Al[tau][kc], Bh[2], Bh[3]);
                        mma16(D[tau][np * 2 + 1], Ah[tau][kc], Bl[2], Bl[3]);
                    }
                }
            }
            {   // x contribution (k8 chunk, cols 64..71)
                const u32 nb8 = (u32)(q * 4 * 8) * SROW + laneB8;
                u32 BhX[4], BlX[4];
                ldmx4(BhX, sb + OFF_HH + nb8);
                ldmx4(BlX, sb + OFF_HL + nb8);
                #pragma unroll
                for (int tau = 0; tau < 2; tau++)
                    #pragma unroll
                    for (int n = 0; n < 4; n++) {
                        mma8(D[tau][n], Ah8[tau], BhX[n]);
                        mma8(D[tau][n], Al8[tau], BhX[n]);
                        mma8(D[tau][n], Ah8[tau], BlX[n]);
                    }
            }
            // ---- epilogue: lane owns k=kml; tile0 = (i,g), tile1 = (f,o) ----
            #pragma unroll
            for (int n = 0; n < 4; n++) {
                #pragma unroll
                for (int par = 0; par < 2; par++) {
                    const int ci = q * 8 + n * 2 + par;
                    const float iv = sig_ap(D[0][n][par] + bi);
                    const float gv = tanh_ap(D[0][n][2 + par] + bg);
                    const float fv = sig_ap(D[1][n][par] + bf);
                    const float ov = sig_ap(D[1][n][2 + par] + bo);
                    const float cn = fmaf(fv, cst[ci], iv * gv);
                    cst[ci] = cn;
                    hst[ci] = ov * tanh_pr(cn);
                }
            }
        }

        __syncthreads();   // all warps done reading hx

        if (t < Tt - 1) {  // x_{t+1}
            const float4 v = *(const float4*)xp;
            const u16 h0 = bfh(v.x), h1 = bfh(v.y), h2 = bfh(v.z), h3 = bfh(v.w);
            *(u32*)(smc + OFF_HH + xdst)     = (u32)h0 | ((u32)h1 << 16);
            *(u32*)(smc + OFF_HH + xdst + 4) = (u32)h2 | ((u32)h3 << 16);
            *(u32*)(smc + OFF_HL + xdst)     = (u32)bfh(v.x - bff(h0)) | ((u32)bfh(v.y - bff(h1)) << 16);
            *(u32*)(smc + OFF_HL + xdst + 4) = (u32)bfh(v.z - bff(h2)) | ((u32)bfh(v.w - bff(h3)) << 16);
            xp += Nn * 8;
        }
        // h_t writeback (hi/lo) to hx[seq][k]
        #pragma unroll
        for (int ci = 0; ci < 32; ci++) {
            const int q = ci >> 3, n = (ci >> 1) & 3, par = ci & 1;
            const int col = (q * 4 + n) * 8 + (l & 3) * 2 + par;   // seq within tile
            const float hv = hst[ci];
            const u16 hi = bfh(hv);
            *(u16*)(smc + OFF_HH + col * SROW + kml * 2) = hi;
            *(u16*)(smc + OFF_HL + col * SROW + kml * 2) = bfh(hv - bff(hi));
        }
        __syncthreads();
    }

    // ---- FC epilogue: y[seq][c] = (hH+hL) . W_fc[c] + b_fc ----
    {
        const int c4 = half * 4;
        float a0 = sBfc[c4], a1 = sBfc[c4 + 1], a2 = sBfc[c4 + 2], a3 = sBfc[c4 + 3];
        #pragma unroll 8
        for (int p = 0; p < 32; p++) {
            const u32 hh = *(const u32*)(smc + OFF_HH + fs * SROW + p * 4);
            const u32 ll = *(const u32*)(smc + OFF_HL + fs * SROW + p * 4);
            const float v0 = bff((u16)hh) + bff((u16)ll);
            const float v1 = bff((u16)(hh >> 16)) + bff((u16)(ll >> 16));
            a0 = fmaf(v0, sWfc[(c4 + 0) * 64 + 2 * p], fmaf(v1, sWfc[(c4 + 0) * 64 + 2 * p + 1], a0));
            a1 = fmaf(v0, sWfc[(c4 + 1) * 64 + 2 * p], fmaf(v1, sWfc[(c4 + 1) * 64 + 2 * p + 1], a1));
            a2 = fmaf(v0, sWfc[(c4 + 2) * 64 + 2 * p], fmaf(v1, sWfc[(c4 + 2) * 64 + 2 * p + 1], a2));
            a3 = fmaf(v0, sWfc[(c4 + 3) * 64 + 2 * p], fmaf(v1, sWfc[(c4 + 3) * 64 + 2 * p + 1], a3));
        }
        float4 y = make_float4(a0, a1, a2, a3);
        *(float4*)(out + (size_t)gseq * 8 + c4) = y;
    }
}

extern "C" void kernel_launch(void* const* d_in, const int* in_sizes, int n_in,
                              void* d_out, int out_size) {
    const float* x    = (const float*)d_in[0];
    const float* W_ih = (const float*)d_in[1];
    const float* W_hh = (const float*)d_in[2];
    const float* b_ih = (const float*)d_in[3];
    const float* b_hh = (const float*)d_in[4];
    const float* W_fc = (const float*)d_in[5];
    const float* b_fc = (const float*)d_in[6];
    float* out = (float*)d_out;

    cudaFuncSetAttribute(lstm_mma_kernel,
                         cudaFuncAttributeMaxDynamicSharedMemorySize, SMEM_BYTES);
    lstm_mma_kernel<<<GRID, THREADS, SMEM_BYTES>>>(
        x, W_ih, W_hh, b_ih, b_hh, W_fc, b_fc, out);
}

// round 11
// speedup vs baseline: 4.0922x; 1.0590x over previous
#include <cuda_runtime.h>
#include <cuda_bf16.h>
#include <cstdint>

typedef uint32_t u32; typedef uint16_t u16;

// Problem constants
constexpr int Tt = 12, Nn = 1370;
constexpr int TILE = 128, THREADS = 512;           // 16 warps
constexpr int GRID = 87680 / TILE;                 // 685

// SMEM layout (bytes). hx row stride 176B (88 bf16) -> conflict-free ldmatrix.
constexpr u32 SROW   = 176;
constexpr u32 PLANE  = 22528;                      // one [128][88] bf16 plane
constexpr u32 HXBUF  = 2 * PLANE;                  // hi+lo planes = 45056
// hx buffer b at b*HXBUF (b=0,1). W staging aliases both (init only):
constexpr u32 OFF_WH  = 0;                         // [256 rows][88] bf16 hi
constexpr u32 OFF_WL  = 45056;                     // lo
constexpr u32 OFF_WFC = 90112;                     // float[8][64]
constexpr u32 OFF_BFC = OFF_WFC + 2048;
constexpr u32 OFF_C   = 92192;                     // float c[128 seq][66]
constexpr u32 SMEM_BYTES = OFF_C + 128 * 66 * 4;   // 125984

__device__ __forceinline__ float tanh_ap(float x) {
    float r; asm("tanh.approx.f32 %0, %1;" : "=f"(r) : "f"(x)); return r;
}
__device__ __forceinline__ float sig_ap(float x) {
    return fmaf(0.5f, tanh_ap(0.5f * x), 0.5f);
}
__device__ __forceinline__ u16 bfh(float v) {
    return __bfloat16_as_ushort(__float2bfloat16(v));
}
__device__ __forceinline__ float bff(u16 b) {
    return __bfloat162float(__ushort_as_bfloat16(b));
}

__device__ __forceinline__ void ldmx4(u32* r, u32 addr) {
    asm volatile("ldmatrix.sync.aligned.m8n8.x4.shared.b16 {%0,%1,%2,%3}, [%4];"
        : "=r"(r[0]), "=r"(r[1]), "=r"(r[2]), "=r"(r[3]) : "r"(addr));
}
__device__ __forceinline__ void ldmx2(u32* r, u32 addr) {
    asm volatile("ldmatrix.sync.aligned.m8n8.x2.shared.b16 {%0,%1}, [%2];"
        : "=r"(r[0]), "=r"(r[1]) : "r"(addr));
}
__device__ __forceinline__ void mma16(float* d, const u32* a, u32 b0, u32 b1) {
    asm volatile("mma.sync.aligned.m16n8k16.row.col.f32.bf16.bf16.f32 "
        "{%0,%1,%2,%3}, {%4,%5,%6,%7}, {%8,%9}, {%0,%1,%2,%3};"
        : "+f"(d[0]), "+f"(d[1]), "+f"(d[2]), "+f"(d[3])
        : "r"(a[0]), "r"(a[1]), "r"(a[2]), "r"(a[3]), "r"(b0), "r"(b1));
}
__device__ __forceinline__ void mma8(float* d, const u32* a, u32 b0) {
    asm volatile("mma.sync.aligned.m16n8k8.row.col.f32.bf16.bf16.f32 "
        "{%0,%1,%2,%3}, {%4,%5}, {%6}, {%0,%1,%2,%3};"
        : "+f"(d[0]), "+f"(d[1]), "+f"(d[2]), "+f"(d[3])
        : "r"(a[0]), "r"(a[1]), "r"(b0));
}

__global__ void __launch_bounds__(THREADS, 1)
lstm_mma16_kernel(const float* __restrict__ x,
                  const float* __restrict__ W_ih,
                  const float* __restrict__ W_hh,
                  const float* __restrict__ b_ih,
                  const float* __restrict__ b_hh,
                  const float* __restrict__ W_fc,
                  const float* __restrict__ b_fc,
                  float* __restrict__ out)
{
    extern __shared__ __align__(16) char smc[];
    const u32 sb = (u32)__cvta_generic_to_shared(smc);

    const int tid = threadIdx.x;
    const int w = tid >> 5, l = tid & 31;
    const int mg = w & 7;                   // M-group: 8 gate-k chunks
    const int ng = w >> 3;                  // seq half: 0 -> 0..63, 1 -> 64..127
    const int grp = l >> 3, lr = l & 7;
    const int kml = (mg << 3) + (l >> 2);   // lane's hidden index k

    float* sWfc = (float*)(smc + OFF_WFC);
    float* sBfc = (float*)(smc + OFF_BFC);
    float* sC   = (float*)(smc + OFF_C);

    // ---- Stage W (hi/lo bf16) in permuted gate-row order (as round 9) ----
    for (int idx = tid; idx < 256 * 72; idx += THREADS) {
        const int p = idx / 72, col = idx % 72;
        const int pw = p >> 5, tau = (p >> 4) & 1, tr = p & 15;
        const int gate = tau ? ((tr < 8) ? 1 : 3) : ((tr < 8) ? 0 : 2);
        const int orig = (gate << 6) + (pw << 3) + (tr & 7);
        const float v = (col < 64) ? W_hh[orig * 64 + col] : W_ih[orig * 8 + (col - 64)];
        const u16 hi = bfh(v);
        *(u16*)(smc + OFF_WH + p * SROW + col * 2) = hi;
        *(u16*)(smc + OFF_WL + p * SROW + col * 2) = bfh(v - bff(hi));
    }
    for (int i = tid; i < 512; i += THREADS) sWfc[i] = W_fc[i];
    if (tid < 8) sBfc[tid] = b_fc[tid];

    const float bi = b_ih[kml]       + b_hh[kml];
    const float bf = b_ih[64 + kml]  + b_hh[64 + kml];
    const float bg = b_ih[128 + kml] + b_hh[128 + kml];
    const float bo = b_ih[192 + kml] + b_hh[192 + kml];

    __syncthreads();

    // ---- Static A (weight) fragments ----
    u32 Ah[2][4][4], Al[2][4][4], Ah8[2][2], Al8[2][2];
    const u32 laneA  = (u32)(((grp & 1) * 8 + lr) * SROW + (grp >> 1) * 16);
    const u32 laneA8 = (u32)((((l >> 3) & 1) * 8 + lr) * SROW + 128);
    #pragma unroll
    for (int tau = 0; tau < 2; tau++) {
        const u32 pr = (u32)(mg * 32 + tau * 16) * SROW;
        #pragma unroll
        for (int kc = 0; kc < 4; kc++) {
            ldmx4(Ah[tau][kc], sb + OFF_WH + pr + laneA + kc * 32);
            ldmx4(Al[tau][kc], sb + OFF_WL + pr + laneA + kc * 32);
        }
        ldmx2(Ah8[tau], sb + OFF_WH + pr + laneA8);
        ldmx2(Al8[tau], sb + OFF_WL + pr + laneA8);
    }
    __syncthreads();   // done reading W staging; region becomes hx buffers

    // ---- Zero hx0 h-cols (both planes) and c ----
    for (int i = tid; i < 128 * 32; i += THREADS) {
        const int row = i >> 5, cp = i & 31;
        *(u32*)(smc + row * SROW + cp * 4)         = 0u;
        *(u32*)(smc + PLANE + row * SROW + cp * 4) = 0u;
    }
    for (int i = tid; i < 128 * 66; i += THREADS) sC[i] = 0.0f;

    // ---- x loader: thread -> (seq = tid/4, channel pair (tid&3)*2) ----
    const int fs = tid >> 2, qc = tid & 3;
    const int gseq = blockIdx.x * TILE + fs;
    const int xb = gseq / Nn, xn = gseq - xb * Nn;
    const float* xp = x + ((size_t)(xb * Tt) * Nn + xn) * 8 + qc * 2;
    const u32 xdst = (u32)(fs * SROW + 128 + qc * 4);
    {   // x_0 -> buffer 0
        const float2 v = *(const float2*)xp;
        const u16 h0 = bfh(v.x), h1 = bfh(v.y);
        *(u32*)(smc + xdst)         = (u32)h0 | ((u32)h1 << 16);
        *(u32*)(smc + PLANE + xdst) = (u32)bfh(v.x - bff(h0)) | ((u32)bfh(v.y - bff(h1)) << 16);
        xp += Nn * 8;
    }
    __syncthreads();

    const u32 laneB  = (u32)(((grp >> 1) * 8 + lr) * SROW + (grp & 1) * 16);
    const u32 laneB8 = (u32)((((l >> 3) & 1) * 8 + (l & 7)) * SROW + 128);

    // =================== time loop ===================
    #pragma unroll 1
    for (int t = 0; t < Tt; ++t) {
        const u32 rb = sb + (u32)(t & 1) * HXBUF;          // read buffer
        const u32 wb = sb + (u32)((t + 1) & 1) * HXBUF;    // write buffer

        #pragma unroll
        for (int p = 0; p < 4; p++) {                       // 4 passes of 2 n-tiles (16 seqs)
            const u32 brow = (u32)(ng * 64 + p * 16) * SROW;
            float D[2][2][4];
            #pragma unroll
            for (int a = 0; a < 2; a++)
                #pragma unroll
                for (int n = 0; n < 2; n++)
                    #pragma unroll
                    for (int r = 0; r < 4; r++) D[a][n][r] = 0.0f;

            #pragma unroll
            for (int kc = 0; kc < 4; kc++) {
                u32 Bh[4], Bl[4];
                const u32 a0 = rb + brow + laneB + (u32)kc * 32;
                ldmx4(Bh, a0);
                ldmx4(Bl, a0 + PLANE);
                #pragma unroll
                for (int tau = 0; tau < 2; tau++) {
                    mma16(D[tau][0], Ah[tau][kc], Bh[0], Bh[1]);
                    mma16(D[tau][0], Al[tau][kc], Bh[0], Bh[1]);
                    mma16(D[tau][0], Ah[tau][kc], Bl[0], Bl[1]);
                    mma16(D[tau][1], Ah[tau][kc], Bh[2], Bh[3]);
                    mma16(D[tau][1], Al[tau][kc], Bh[2], Bh[3]);
                    mma16(D[tau][1], Ah[tau][kc], Bl[2], Bl[3]);
                }
            }
            {   // x contribution (cols 64..71)
                u32 BhX[2], BlX[2];
                const u32 ax = rb + brow + laneB8;
                ldmx2(BhX, ax);
                ldmx2(BlX, ax + PLANE);
                #pragma unroll
                for (int tau = 0; tau < 2; tau++)
                    #pragma unroll
                    for (int nt = 0; nt < 2; nt++) {
                        mma8(D[tau][nt], Ah8[tau], BhX[nt]);
                        mma8(D[tau][nt], Al8[tau], BhX[nt]);
                        mma8(D[tau][nt], Ah8[tau], BlX[nt]);
                    }
            }
            // ---- epilogue: lane owns k=kml; tau0 = (i,g), tau1 = (f,o) ----
            #pragma unroll
            for (int nt = 0; nt < 2; nt++) {
                #pragma unroll
                for (int par = 0; par < 2; par++) {
                    const int s = ng * 64 + p * 16 + nt * 8 + (l & 3) * 2 + par;
                    const float iv = sig_ap(D[0][nt][par] + bi);
                    const float gv = tanh_ap(D[0][nt][2 + par] + bg);
                    const float fv = sig_ap(D[1][nt][par] + bf);
                    const float ov = sig_ap(D[1][nt][2 + par] + bo);
                    float* cp = sC + s * 66 + kml;
                    const float cn = fmaf(fv, *cp, iv * gv);
                    *cp = cn;
                    const float hv = ov * tanh_ap(cn);
                    const u16 hi = bfh(hv);
                    *(u16*)(smc + (wb - sb) + s * SROW + kml * 2)         = hi;
                    *(u16*)(smc + (wb - sb) + PLANE + s * SROW + kml * 2) = bfh(hv - bff(hi));
                }
            }
        }

        if (t < Tt - 1) {   // x_{t+1} -> write buffer
            const float2 v = *(const float2*)xp;
            const u16 h0 = bfh(v.x), h1 = bfh(v.y);
            *(u32*)(smc + (wb - sb) + xdst)         = (u32)h0 | ((u32)h1 << 16);
            *(u32*)(smc + (wb - sb) + PLANE + xdst) = (u32)bfh(v.x - bff(h0)) | ((u32)bfh(v.y - bff(h1)) << 16);
            xp += Nn * 8;
        }
        __syncthreads();    // h_t + x_{t+1} in write buffer visible to all
    }

    // ---- FC epilogue: final h is in buffer 0 (Tt even) ----
    {
        const int c2 = qc * 2;
        float a0 = sBfc[c2], a1 = sBfc[c2 + 1];
        #pragma unroll 8
        for (int p = 0; p < 32; p++) {
            const u32 hh = *(const u32*)(smc + fs * SROW + p * 4);
            const u32 ll = *(const u32*)(smc + PLANE + fs * SROW + p * 4);
            const float v0 = bff((u16)hh) + bff((u16)ll);
            const float v1 = bff((u16)(hh >> 16)) + bff((u16)(ll >> 16));
            a0 = fmaf(v0, sWfc[(c2 + 0) * 64 + 2 * p], fmaf(v1, sWfc[(c2 + 0) * 64 + 2 * p + 1], a0));
            a1 = fmaf(v0, sWfc[(c2 + 1) * 64 + 2 * p], fmaf(v1, sWfc[(c2 + 1) * 64 + 2 * p + 1], a1));
        }
        *(float2*)(out + (size_t)gseq * 8 + c2) = make_float2(a0, a1);
    }
}

extern "C" void kernel_launch(void* const* d_in, const int* in_sizes, int n_in,
                              void* d_out, int out_size) {
    const float* x    = (const float*)d_in[0];
    const float* W_ih = (const float*)d_in[1];
    const float* W_hh = (const float*)d_in[2];
    const float* b_ih = (const float*)d_in[3];
    const float* b_hh = (const float*)d_in[4];
    const float* W_fc = (const float*)d_in[5];
    const float* b_fc = (const float*)d_in[6];
    float* out = (float*)d_out;

    cudaFuncSetAttribute(lstm_mma16_kernel,
                         cudaFuncAttributeMaxDynamicSharedMemorySize, SMEM_BYTES);
    lstm_mma16_kernel<<<GRID, THREADS, SMEM_BYTES>>>(
        x, W_ih, W_hh, b_ih, b_hh, W_fc, b_fc, out);
}

// round 14
// speedup vs baseline: 4.3085x; 1.0529x over previous
#include <cuda_runtime.h>
#include <cuda_bf16.h>
#include <cstdint>

typedef uint32_t u32; typedef uint16_t u16;

// Problem constants
constexpr int Tt = 12, Nn = 1370;
constexpr int TILE = 128, THREADS = 512;           // 16 warps
constexpr int GRID = 87680 / TILE;                 // 685

// SMEM layout (bytes). hx row stride 176B (88 bf16) -> conflict-free ldmatrix.
constexpr u32 SROW   = 176;
constexpr u32 PLANE  = 22528;                      // one [128][88] bf16 plane
constexpr u32 HXBUF  = 2 * PLANE;                  // hi+lo planes = 45056
// hx buffer b at b*HXBUF (b=0,1). W staging aliases both (init only):
constexpr u32 OFF_WH  = 0;                         // [256 rows][88] bf16 hi
constexpr u32 OFF_WL  = 45056;                     // lo
constexpr u32 OFF_WFC = 90112;                     // float[8][64]
constexpr u32 OFF_BFC = OFF_WFC + 2048;
constexpr u32 OFF_C   = 92192;                     // float c[128 seq][66]
constexpr u32 SMEM_BYTES = OFF_C + 128 * 66 * 4;   // 125984

__device__ __forceinline__ float tanh_ap(float x) {
    float r; asm("tanh.approx.f32 %0, %1;" : "=f"(r) : "f"(x)); return r;
}
__device__ __forceinline__ float sig_ap(float x) {
    return fmaf(0.5f, tanh_ap(0.5f * x), 0.5f);
}
__device__ __forceinline__ u16 bfh(float v) {
    return __bfloat16_as_ushort(__float2bfloat16(v));
}
__device__ __forceinline__ float bff(u16 b) {
    return __bfloat162float(__ushort_as_bfloat16(b));
}

__device__ __forceinline__ void ldmx4(u32* r, u32 addr) {
    asm volatile("ldmatrix.sync.aligned.m8n8.x4.shared.b16 {%0,%1,%2,%3}, [%4];"
        : "=r"(r[0]), "=r"(r[1]), "=r"(r[2]), "=r"(r[3]) : "r"(addr));
}
__device__ __forceinline__ void ldmx2(u32* r, u32 addr) {
    asm volatile("ldmatrix.sync.aligned.m8n8.x2.shared.b16 {%0,%1}, [%2];"
        : "=r"(r[0]), "=r"(r[1]) : "r"(addr));
}
__device__ __forceinline__ void mma16(float* d, const u32* a, u32 b0, u32 b1) {
    asm volatile("mma.sync.aligned.m16n8k16.row.col.f32.bf16.bf16.f32 "
        "{%0,%1,%2,%3}, {%4,%5,%6,%7}, {%8,%9}, {%0,%1,%2,%3};"
        : "+f"(d[0]), "+f"(d[1]), "+f"(d[2]), "+f"(d[3])
        : "r"(a[0]), "r"(a[1]), "r"(a[2]), "r"(a[3]), "r"(b0), "r"(b1));
}
__device__ __forceinline__ void mma8(float* d, const u32* a, u32 b0) {
    asm volatile("mma.sync.aligned.m16n8k8.row.col.f32.bf16.bf16.f32 "
        "{%0,%1,%2,%3}, {%4,%5}, {%6}, {%0,%1,%2,%3};"
        : "+f"(d[0]), "+f"(d[1]), "+f"(d[2]), "+f"(d[3])
        : "r"(a[0]), "r"(a[1]), "r"(b0));
}

__global__ void __launch_bounds__(THREADS, 1)
lstm_pipe_kernel(const float* __restrict__ x,
                 const float* __restrict__ W_ih,
                 const float* __restrict__ W_hh,
                 const float* __restrict__ b_ih,
                 const float* __restrict__ b_hh,
                 const float* __restrict__ W_fc,
                 const float* __restrict__ b_fc,
                 float* __restrict__ out)
{
    extern __shared__ __align__(16) char smc[];
    const u32 sb = (u32)__cvta_generic_to_shared(smc);

    const int tid = threadIdx.x;
    const int w = tid >> 5, l = tid & 31;
    const int mg = w & 7;                   // M-group: 8 gate-k chunks
    const int ng = w >> 3;                  // seq half: 0 -> 0..63, 1 -> 64..127
    const int grp = l >> 3, lr = l & 7;
    const int kml = (mg << 3) + (l >> 2);   // lane's hidden index k

    float* sWfc = (float*)(smc + OFF_WFC);
    float* sBfc = (float*)(smc + OFF_BFC);
    float* sC   = (float*)(smc + OFF_C);

    // ---- Stage W (hi/lo bf16) in permuted gate-row order ----
    for (int idx = tid; idx < 256 * 72; idx += THREADS) {
        const int p = idx / 72, col = idx % 72;
        const int pw = p >> 5, tau = (p >> 4) & 1, tr = p & 15;
        const int gate = tau ? ((tr < 8) ? 1 : 3) : ((tr < 8) ? 0 : 2);
        const int orig = (gate << 6) + (pw << 3) + (tr & 7);
        const float v = (col < 64) ? W_hh[orig * 64 + col] : W_ih[orig * 8 + (col - 64)];
        const u16 hi = bfh(v);
        *(u16*)(smc + OFF_WH + p * SROW + col * 2) = hi;
        *(u16*)(smc + OFF_WL + p * SROW + col * 2) = bfh(v - bff(hi));
    }
    for (int i = tid; i < 512; i += THREADS) sWfc[i] = W_fc[i];
    if (tid < 8) sBfc[tid] = b_fc[tid];

    const float bi = b_ih[kml]       + b_hh[kml];
    const float bf = b_ih[64 + kml]  + b_hh[64 + kml];
    const float bg = b_ih[128 + kml] + b_hh[128 + kml];
    const float bo = b_ih[192 + kml] + b_hh[192 + kml];

    __syncthreads();

    // ---- Static A (weight) fragments ----
    u32 Ah[2][4][4], Al[2][4][4], Ah8[2][2], Al8[2][2];
    const u32 laneA  = (u32)(((grp & 1) * 8 + lr) * SROW + (grp >> 1) * 16);
    const u32 laneA8 = (u32)((((l >> 3) & 1) * 8 + lr) * SROW + 128);
    #pragma unroll
    for (int tau = 0; tau < 2; tau++) {
        const u32 pr = (u32)(mg * 32 + tau * 16) * SROW;
        #pragma unroll
        for (int kc = 0; kc < 4; kc++) {
            ldmx4(Ah[tau][kc], sb + OFF_WH + pr + laneA + kc * 32);
            ldmx4(Al[tau][kc], sb + OFF_WL + pr + laneA + kc * 32);
        }
        ldmx2(Ah8[tau], sb + OFF_WH + pr + laneA8);
        ldmx2(Al8[tau], sb + OFF_WL + pr + laneA8);
    }
    __syncthreads();   // done reading W staging; region becomes hx buffers

    // ---- Zero hx0 h-cols (both planes) and c ----
    for (int i = tid; i < 128 * 32; i += THREADS) {
        const int row = i >> 5, cp = i & 31;
        *(u32*)(smc + row * SROW + cp * 4)         = 0u;
        *(u32*)(smc + PLANE + row * SROW + cp * 4) = 0u;
    }
    for (int i = tid; i < 128 * 66; i += THREADS) sC[i] = 0.0f;

    // ---- x loader: thread -> (seq = tid/4, channel pair (tid&3)*2) ----
    const int fs = tid >> 2, qc = tid & 3;
    const int gseq = blockIdx.x * TILE + fs;
    const int xb = gseq / Nn, xn = gseq - xb * Nn;
    const float* xp = x + ((size_t)(xb * Tt) * Nn + xn) * 8 + qc * 2;
    const u32 xdst = (u32)(fs * SROW + 128 + qc * 4);
    {   // x_0 -> buffer 0
        const float2 v = *(const float2*)xp;
        const u16 h0 = bfh(v.x), h1 = bfh(v.y);
        *(u32*)(smc + xdst)         = (u32)h0 | ((u32)h1 << 16);
        *(u32*)(smc + PLANE + xdst) = (u32)bfh(v.x - bff(h0)) | ((u32)bfh(v.y - bff(h1)) << 16);
        xp += Nn * 8;
    }
    __syncthreads();

    const u32 laneB  = (u32)(((grp >> 1) * 8 + lr) * SROW + (grp & 1) * 16);
    const u32 laneB8 = (u32)((((l >> 3) & 1) * 8 + (l & 7)) * SROW + 128);
    const int  sE    = ng * 64 + (l & 3) * 2;   // epilogue base seq for this lane

    // =================== time loop ===================
    #pragma unroll 1
    for (int t = 0; t < Tt; ++t) {
        const u32 rb  = sb + (u32)(t & 1) * HXBUF;          // read buffer
        const u32 wbo = (u32)((t + 1) & 1) * HXBUF;         // write buffer offset

        float D[2][2][2][4];    // [pipeline buf][tau][nt][4]

        // ---- pipelined passes: MMA(p) issued before epilogue(p-1) ----
        #pragma unroll
        for (int p = 0; p < 4; p++) {
            const int db = p & 1;
            #pragma unroll
            for (int a = 0; a < 2; a++)
                #pragma unroll
                for (int n = 0; n < 2; n++)
                    #pragma unroll
                    for (int r = 0; r < 4; r++) D[db][a][n][r] = 0.0f;

            const u32 brow = (u32)(ng * 64 + p * 16) * SROW;
            #pragma unroll
            for (int kc = 0; kc < 4; kc++) {
                u32 Bh[4], Bl[4];
                const u32 a0 = rb + brow + laneB + (u32)kc * 32;
                ldmx4(Bh, a0);
                ldmx4(Bl, a0 + PLANE);
                #pragma unroll
                for (int tau = 0; tau < 2; tau++) {
                    mma16(D[db][tau][0], Ah[tau][kc], Bh[0], Bh[1]);
                    mma16(D[db][tau][0], Al[tau][kc], Bh[0], Bh[1]);
                    mma16(D[db][tau][0], Ah[tau][kc], Bl[0], Bl[1]);
                    mma16(D[db][tau][1], Ah[tau][kc], Bh[2], Bh[3]);
                    mma16(D[db][tau][1], Al[tau][kc], Bh[2], Bh[3]);
                    mma16(D[db][tau][1], Ah[tau][kc], Bl[2], Bl[3]);
                }
            }
            {   // x contribution (cols 64..71)
                u32 BhX[2], BlX[2];
                const u32 ax = rb + brow + laneB8;
                ldmx2(BhX, ax);
                ldmx2(BlX, ax + PLANE);
                #pragma unroll
                for (int tau = 0; tau < 2; tau++)
                    #pragma unroll
                    for (int nt = 0; nt < 2; nt++) {
                        mma8(D[db][tau][nt], Ah8[tau], BhX[nt]);
                        mma8(D[db][tau][nt], Al8[tau], BhX[nt]);
                        mma8(D[db][tau][nt], Ah8[tau], BlX[nt]);
                    }
            }

            // ---- epilogue of previous pass (overlaps with this pass's MMAs) ----
            if (p > 0) {
                const int pe = p - 1, eb = 1 - db;
                #pragma unroll
                for (int nt = 0; nt < 2; nt++) {
                    #pragma unroll
                    for (int par = 0; par < 2; par++) {
                        const int s = sE + pe * 16 + nt * 8 + par;
                        const float iv = sig_ap(D[eb][0][nt][par] + bi);
                        const float gv = tanh_ap(D[eb][0][nt][2 + par] + bg);
                        const float fv = sig_ap(D[eb][1][nt][par] + bf);
                        const float ov = sig_ap(D[eb][1][nt][2 + par] + bo);
                        float* cp = sC + s * 66 + kml;
                        const float cn = fmaf(fv, *cp, iv * gv);
                        *cp = cn;
                        const float hv = ov * tanh_ap(cn);
                        const u16 hi = bfh(hv);
                        *(u16*)(smc + wbo + s * SROW + kml * 2)         = hi;
                        *(u16*)(smc + wbo + PLANE + s * SROW + kml * 2) = bfh(hv - bff(hi));
                    }
                }
            }
        }
        {   // final epilogue (pass 3, buffer 1)
            #pragma unroll
            for (int nt = 0; nt < 2; nt++) {
                #pragma unroll
                for (int par = 0; par < 2; par++) {
                    const int s = sE + 3 * 16 + nt * 8 + par;
                    const float iv = sig_ap(D[1][0][nt][par] + bi);
                    const float gv = tanh_ap(D[1][0][nt][2 + par] + bg);
                    const float fv = sig_ap(D[1][1][nt][par] + bf);
                    const float ov = sig_ap(D[1][1][nt][2 + par] + bo);
                    float* cp = sC + s * 66 + kml;
                    const float cn = fmaf(fv, *cp, iv * gv);
                    *cp = cn;
                    const float hv = ov * tanh_ap(cn);
                    const u16 hi = bfh(hv);
                    *(u16*)(smc + wbo + s * SROW + kml * 2)         = hi;
                    *(u16*)(smc + wbo + PLANE + s * SROW + kml * 2) = bfh(hv - bff(hi));
                }
            }
        }

        if (t < Tt - 1) {   // x_{t+1} -> write buffer
            const float2 v = *(const float2*)xp;
            const u16 h0 = bfh(v.x), h1 = bfh(v.y);
            *(u32*)(smc + wbo + xdst)         = (u32)h0 | ((u32)h1 << 16);
            *(u32*)(smc + wbo + PLANE + xdst) = (u32)bfh(v.x - bff(h0)) | ((u32)bfh(v.y - bff(h1)) << 16);
            xp += Nn * 8;
        }
        __syncthreads();    // h_t + x_{t+1} in write buffer visible to all
    }

    // ---- FC epilogue: final h is in buffer 0 (Tt even) ----
    {
        const int c2 = qc * 2;
        float a0 = sBfc[c2], a1 = sBfc[c2 + 1];
        #pragma unroll 8
        for (int p = 0; p < 32; p++) {
            const u32 hh = *(const u32*)(smc + fs * SROW + p * 4);
            const u32 ll = *(const u32*)(smc + PLANE + fs * SROW + p * 4);
            const float v0 = bff((u16)hh) + bff((u16)ll);
            const float v1 = bff((u16)(hh >> 16)) + bff((u16)(ll >> 16));
            a0 = fmaf(v0, sWfc[(c2 + 0) * 64 + 2 * p], fmaf(v1, sWfc[(c2 + 0) * 64 + 2 * p + 1], a0));
            a1 = fmaf(v0, sWfc[(c2 + 1) * 64 + 2 * p], fmaf(v1, sWfc[(c2 + 1) * 64 + 2 * p + 1], a1));
        }
        *(float2*)(out + (size_t)gseq * 8 + c2) = make_float2(a0, a1);
    }
}

extern "C" void kernel_launch(void* const* d_in, const int* in_sizes, int n_in,
                              void* d_out, int out_size) {
    const float* x    = (const float*)d_in[0];
    const float* W_ih = (const float*)d_in[1];
    const float* W_hh = (const float*)d_in[2];
    const float* b_ih = (const float*)d_in[3];
    const float* b_hh = (const float*)d_in[4];
    const float* W_fc = (const float*)d_in[5];
    const float* b_fc = (const float*)d_in[6];
    float* out = (float*)d_out;

    cudaFuncSetAttribute(lstm_pipe_kernel,
                         cudaFuncAttributeMaxDynamicSharedMemorySize, SMEM_BYTES);
    lstm_pipe_kernel<<<GRID, THREADS, SMEM_BYTES>>>(
        x, W_ih, W_hh, b_ih, b_hh, W_fc, b_fc, out);
}

// round 15
// speedup vs baseline: 5.8615x; 1.3604x over previous
#include <cuda_runtime.h>
#include <cuda_fp16.h>
#include <cstdint>

typedef uint32_t u32; typedef uint16_t u16;

// Problem constants
constexpr int Tt = 12, Nn = 1370;
constexpr int TILE = 128, THREADS = 512;           // 16 warps
constexpr int GRID = 87680 / TILE;                 // 685

// SMEM layout (bytes). hx row stride 176B (88 fp16) -> conflict-free ldmatrix.
constexpr u32 SROW   = 176;
constexpr u32 PLANE  = 22528;                      // one [128][88] fp16 plane
// hx buffer b (single plane each) at b*PLANE (b=0,1). W staging aliases (init only):
constexpr u32 OFF_WH  = 0;                         // [256 rows][88] fp16 hi
constexpr u32 OFF_WL  = 45056;                     // fp16 lo (subnormals OK)
constexpr u32 OFF_WFC = 90112;                     // float[8][64]
constexpr u32 OFF_BFC = OFF_WFC + 2048;
constexpr u32 OFF_C   = 92192;                     // float c[128 seq][66]
constexpr u32 SMEM_BYTES = OFF_C + 128 * 66 * 4;   // 125984

__device__ __forceinline__ float tanh_ap(float x) {
    float r; asm("tanh.approx.f32 %0, %1;" : "=f"(r) : "f"(x)); return r;
}
__device__ __forceinline__ float sig_ap(float x) {
    return fmaf(0.5f, tanh_ap(0.5f * x), 0.5f);
}
__device__ __forceinline__ u16 fph(float v) {
    return __half_as_ushort(__float2half_rn(v));
}
__device__ __forceinline__ float fhf(u16 b) {
    return __half2float(__ushort_as_half(b));
}

__device__ __forceinline__ void ldmx4(u32* r, u32 addr) {
    asm volatile("ldmatrix.sync.aligned.m8n8.x4.shared.b16 {%0,%1,%2,%3}, [%4];"
        : "=r"(r[0]), "=r"(r[1]), "=r"(r[2]), "=r"(r[3]) : "r"(addr));
}
__device__ __forceinline__ void ldmx2(u32* r, u32 addr) {
    asm volatile("ldmatrix.sync.aligned.m8n8.x2.shared.b16 {%0,%1}, [%2];"
        : "=r"(r[0]), "=r"(r[1]) : "r"(addr));
}
__device__ __forceinline__ void mma16(float* d, const u32* a, u32 b0, u32 b1) {
    asm volatile("mma.sync.aligned.m16n8k16.row.col.f32.f16.f16.f32 "
        "{%0,%1,%2,%3}, {%4,%5,%6,%7}, {%8,%9}, {%0,%1,%2,%3};"
        : "+f"(d[0]), "+f"(d[1]), "+f"(d[2]), "+f"(d[3])
        : "r"(a[0]), "r"(a[1]), "r"(a[2]), "r"(a[3]), "r"(b0), "r"(b1));
}
__device__ __forceinline__ void mma8(float* d, const u32* a, u32 b0) {
    asm volatile("mma.sync.aligned.m16n8k8.row.col.f32.f16.f16.f32 "
        "{%0,%1,%2,%3}, {%4,%5}, {%6}, {%0,%1,%2,%3};"
        : "+f"(d[0]), "+f"(d[1]), "+f"(d[2]), "+f"(d[3])
        : "r"(a[0]), "r"(a[1]), "r"(b0));
}

__global__ void __launch_bounds__(THREADS, 1)
lstm_h16_kernel(const float* __restrict__ x,
                const float* __restrict__ W_ih,
                const float* __restrict__ W_hh,
                const float* __restrict__ b_ih,
                const float* __restrict__ b_hh,
                const float* __restrict__ W_fc,
                const float* __restrict__ b_fc,
                float* __restrict__ out)
{
    extern __shared__ __align__(16) char smc[];
    const u32 sb = (u32)__cvta_generic_to_shared(smc);

    const int tid = threadIdx.x;
    const int w = tid >> 5, l = tid & 31;
    const int mg = w & 7;                   // M-group: 8 gate-k chunks
    const int ng = w >> 3;                  // seq half: 0 -> 0..63, 1 -> 64..127
    const int grp = l >> 3, lr = l & 7;
    const int kml = (mg << 3) + (l >> 2);   // lane's hidden index k

    float* sWfc = (float*)(smc + OFF_WFC);
    float* sBfc = (float*)(smc + OFF_BFC);
    float* sC   = (float*)(smc + OFF_C);

    // ---- Stage W (hi/lo fp16) in permuted gate-row order ----
    // permuted row p = 32w + 16*tau + tr:
    //   tau=0: tr<8 -> i_{8w+tr}, tr>=8 -> g_{8w+tr-8}
    //   tau=1: tr<8 -> f_{8w+tr}, tr>=8 -> o_{8w+tr-8}
    for (int idx = tid; idx < 256 * 72; idx += THREADS) {
        const int p = idx / 72, col = idx % 72;
        const int pw = p >> 5, tau = (p >> 4) & 1, tr = p & 15;
        const int gate = tau ? ((tr < 8) ? 1 : 3) : ((tr < 8) ? 0 : 2);
        const int orig = (gate << 6) + (pw << 3) + (tr & 7);
        const float v = (col < 64) ? W_hh[orig * 64 + col] : W_ih[orig * 8 + (col - 64)];
        const u16 hi = fph(v);
        *(u16*)(smc + OFF_WH + p * SROW + col * 2) = hi;
        *(u16*)(smc + OFF_WL + p * SROW + col * 2) = fph(v - fhf(hi));
    }
    for (int i = tid; i < 512; i += THREADS) sWfc[i] = W_fc[i];
    if (tid < 8) sBfc[tid] = b_fc[tid];

    const float bi = b_ih[kml]       + b_hh[kml];
    const float bf = b_ih[64 + kml]  + b_hh[64 + kml];
    const float bg = b_ih[128 + kml] + b_hh[128 + kml];
    const float bo = b_ih[192 + kml] + b_hh[192 + kml];

    __syncthreads();

    // ---- Static A (weight) fragments: fp16 hi + fp16 lo ----
    u32 Ah[2][4][4], Al[2][4][4], Ah8[2][2], Al8[2][2];
    const u32 laneA  = (u32)(((grp & 1) * 8 + lr) * SROW + (grp >> 1) * 16);
    const u32 laneA8 = (u32)((((l >> 3) & 1) * 8 + lr) * SROW + 128);
    #pragma unroll
    for (int tau = 0; tau < 2; tau++) {
        const u32 pr = (u32)(mg * 32 + tau * 16) * SROW;
        #pragma unroll
        for (int kc = 0; kc < 4; kc++) {
            ldmx4(Ah[tau][kc], sb + OFF_WH + pr + laneA + kc * 32);
            ldmx4(Al[tau][kc], sb + OFF_WL + pr + laneA + kc * 32);
        }
        ldmx2(Ah8[tau], sb + OFF_WH + pr + laneA8);
        ldmx2(Al8[tau], sb + OFF_WL + pr + laneA8);
    }
    __syncthreads();   // done reading W staging; region becomes hx buffers

    // ---- Zero hx buffer 0 h-cols and c ----
    for (int i = tid; i < 128 * 32; i += THREADS) {
        const int row = i >> 5, cp = i & 31;
        *(u32*)(smc + row * SROW + cp * 4) = 0u;
    }
    for (int i = tid; i < 128 * 66; i += THREADS) sC[i] = 0.0f;

    // ---- x loader: thread -> (seq = tid/4, channel pair (tid&3)*2) ----
    const int fs = tid >> 2, qc = tid & 3;
    const int gseq = blockIdx.x * TILE + fs;
    const int xb = gseq / Nn, xn = gseq - xb * Nn;
    const float* xp = x + ((size_t)(xb * Tt) * Nn + xn) * 8 + qc * 2;
    const u32 xdst = (u32)(fs * SROW + 128 + qc * 4);
    {   // x_0 -> buffer 0 (single fp16 plane)
        const float2 v = *(const float2*)xp;
        *(u32*)(smc + xdst) = (u32)fph(v.x) | ((u32)fph(v.y) << 16);
        xp += Nn * 8;
    }
    __syncthreads();

    const u32 laneB  = (u32)(((grp >> 1) * 8 + lr) * SROW + (grp & 1) * 16);
    const u32 laneB8 = (u32)((((l >> 3) & 1) * 8 + (l & 7)) * SROW + 128);
    const int  sE    = ng * 64 + (l & 3) * 2;   // epilogue base seq for this lane

    // =================== time loop ===================
    #pragma unroll 1
    for (int t = 0; t < Tt; ++t) {
        const u32 rb  = sb + (u32)(t & 1) * PLANE;          // read buffer
        const u32 wbo = (u32)((t + 1) & 1) * PLANE;         // write buffer offset

        float D[2][2][2][4];    // [pipeline buf][tau][nt][4]

        // ---- pipelined passes: MMA(p) issued before epilogue(p-1) ----
        #pragma unroll
        for (int p = 0; p < 4; p++) {
            const int db = p & 1;
            #pragma unroll
            for (int a = 0; a < 2; a++)
                #pragma unroll
                for (int n = 0; n < 2; n++)
                    #pragma unroll
                    for (int r = 0; r < 4; r++) D[db][a][n][r] = 0.0f;

            const u32 brow = (u32)(ng * 64 + p * 16) * SROW;
            #pragma unroll
            for (int kc = 0; kc < 4; kc++) {
                u32 Bh[4];
                ldmx4(Bh, rb + brow + laneB + (u32)kc * 32);
                #pragma unroll
                for (int tau = 0; tau < 2; tau++) {
                    mma16(D[db][tau][0], Ah[tau][kc], Bh[0], Bh[1]);
                    mma16(D[db][tau][0], Al[tau][kc], Bh[0], Bh[1]);
                    mma16(D[db][tau][1], Ah[tau][kc], Bh[2], Bh[3]);
                    mma16(D[db][tau][1], Al[tau][kc], Bh[2], Bh[3]);
                }
            }
            {   // x contribution (cols 64..71)
                u32 BhX[2];
                ldmx2(BhX, rb + brow + laneB8);
                #pragma unroll
                for (int tau = 0; tau < 2; tau++)
                    #pragma unroll
                    for (int nt = 0; nt < 2; nt++) {
                        mma8(D[db][tau][nt], Ah8[tau], BhX[nt]);
                        mma8(D[db][tau][nt], Al8[tau], BhX[nt]);
                    }
            }

            // ---- epilogue of previous pass (overlaps with this pass's MMAs) ----
            if (p > 0) {
                const int pe = p - 1, eb = 1 - db;
                #pragma unroll
                for (int nt = 0; nt < 2; nt++) {
                    #pragma unroll
                    for (int par = 0; par < 2; par++) {
                        const int s = sE + pe * 16 + nt * 8 + par;
                        const float iv = sig_ap(D[eb][0][nt][par] + bi);
                        const float gv = tanh_ap(D[eb][0][nt][2 + par] + bg);
                        const float fv = sig_ap(D[eb][1][nt][par] + bf);
                        const float ov = sig_ap(D[eb][1][nt][2 + par] + bo);
                        float* cp = sC + s * 66 + kml;
                        const float cn = fmaf(fv, *cp, iv * gv);
                        *cp = cn;
                        const float hv = ov * tanh_ap(cn);
                        *(u16*)(smc + wbo + s * SROW + kml * 2) = fph(hv);
                    }
                }
            }
        }
        {   // final epilogue (pass 3, buffer 1)
            #pragma unroll
            for (int nt = 0; nt < 2; nt++) {
                #pragma unroll
                for (int par = 0; par < 2; par++) {
                    const int s = sE + 3 * 16 + nt * 8 + par;
                    const float iv = sig_ap(D[1][0][nt][par] + bi);
                    const float gv = tanh_ap(D[1][0][nt][2 + par] + bg);
                    const float fv = sig_ap(D[1][1][nt][par] + bf);
                    const float ov = sig_ap(D[1][1][nt][2 + par] + bo);
                    float* cp = sC + s * 66 + kml;
                    const float cn = fmaf(fv, *cp, iv * gv);
                    *cp = cn;
                    const float hv = ov * tanh_ap(cn);
                    *(u16*)(smc + wbo + s * SROW + kml * 2) = fph(hv);
                }
            }
        }

        if (t < Tt - 1) {   // x_{t+1} -> write buffer
            const float2 v = *(const float2*)xp;
            *(u32*)(smc + wbo + xdst) = (u32)fph(v.x) | ((u32)fph(v.y) << 16);
            xp += Nn * 8;
        }
        __syncthreads();    // h_t + x_{t+1} in write buffer visible to all
    }

    // ---- FC epilogue: final h is in buffer 0 (Tt even) ----
    {
        const int c2 = qc * 2;
        float a0 = sBfc[c2], a1 = sBfc[c2 + 1];
        #pragma unroll 8
        for (int p = 0; p < 32; p++) {
            const u32 hh = *(const u32*)(smc + fs * SROW + p * 4);
            const float v0 = fhf((u16)hh);
            const float v1 = fhf((u16)(hh >> 16));
            a0 = fmaf(v0, sWfc[(c2 + 0) * 64 + 2 * p], fmaf(v1, sWfc[(c2 + 0) * 64 + 2 * p + 1], a0));
            a1 = fmaf(v0, sWfc[(c2 + 1) * 64 + 2 * p], fmaf(v1, sWfc[(c2 + 1) * 64 + 2 * p + 1], a1));
        }
        *(float2*)(out + (size_t)gseq * 8 + c2) = make_float2(a0, a1);
    }
}

extern "C" void kernel_launch(void* const* d_in, const int* in_sizes, int n_in,
                              void* d_out, int out_size) {
    const float* x    = (const float*)d_in[0];
    const float* W_ih = (const float*)d_in[1];
    const float* W_hh = (const float*)d_in[2];
    const float* b_ih = (const float*)d_in[3];
    const float* b_hh = (const float*)d_in[4];
    const float* W_fc = (const float*)d_in[5];
    const float* b_fc = (const float*)d_in[6];
    float* out = (float*)d_out;

    cudaFuncSetAttribute(lstm_h16_kernel,
                         cudaFuncAttributeMaxDynamicSharedMemorySize, SMEM_BYTES);
    lstm_h16_kernel<<<GRID, THREADS, SMEM_BYTES>>>(
        x, W_ih, W_hh, b_ih, b_hh, W_fc, b_fc, out);
}

// round 17
// speedup vs baseline: 7.5404x; 1.2864x over previous
#include <cuda_runtime.h>
#include <cuda_fp16.h>
#include <cstdint>

typedef uint32_t u32; typedef uint16_t u16;

// Problem constants
constexpr int Tt = 12, Nn = 1370;
constexpr int TILE = 128, THREADS = 512;           // 16 warps
constexpr int GRID = 87680 / TILE;                 // 685

// SMEM layout (bytes). hx row stride 176B (88 fp16) -> conflict-free ldmatrix.
constexpr u32 SROW   = 176;
constexpr u32 PLANE  = 22528;                      // one [128][88] fp16 plane
// hx buffer b at b*PLANE (b=0,1). W staging ([256][88] = 45056B) aliases both (init only).
constexpr u32 OFF_WH  = 0;
constexpr u32 OFF_WFC = 45056;                     // float[8][64]
constexpr u32 OFF_BFC = OFF_WFC + 2048;
constexpr u32 SMEM_BYTES = OFF_BFC + 32;           // 47136

__device__ __forceinline__ float tanh_ap(float x) {
    float r; asm("tanh.approx.f32 %0, %1;" : "=f"(r) : "f"(x)); return r;
}
__device__ __forceinline__ float sig_ap(float x) {
    return fmaf(0.5f, tanh_ap(0.5f * x), 0.5f);
}
__device__ __forceinline__ u16 fph(float v) {
    return __half_as_ushort(__float2half_rn(v));
}
__device__ __forceinline__ float fhf(u16 b) {
    return __half2float(__ushort_as_half(b));
}

__device__ __forceinline__ void ldmx4(u32* r, u32 addr) {
    asm volatile("ldmatrix.sync.aligned.m8n8.x4.shared.b16 {%0,%1,%2,%3}, [%4];"
        : "=r"(r[0]), "=r"(r[1]), "=r"(r[2]), "=r"(r[3]) : "r"(addr));
}
__device__ __forceinline__ void ldmx2(u32* r, u32 addr) {
    asm volatile("ldmatrix.sync.aligned.m8n8.x2.shared.b16 {%0,%1}, [%2];"
        : "=r"(r[0]), "=r"(r[1]) : "r"(addr));
}
__device__ __forceinline__ void mma16(float* d, const u32* a, u32 b0, u32 b1) {
    asm volatile("mma.sync.aligned.m16n8k16.row.col.f32.f16.f16.f32 "
        "{%0,%1,%2,%3}, {%4,%5,%6,%7}, {%8,%9}, {%0,%1,%2,%3};"
        : "+f"(d[0]), "+f"(d[1]), "+f"(d[2]), "+f"(d[3])
        : "r"(a[0]), "r"(a[1]), "r"(a[2]), "r"(a[3]), "r"(b0), "r"(b1));
}
__device__ __forceinline__ void mma8(float* d, const u32* a, u32 b0) {
    asm volatile("mma.sync.aligned.m16n8k8.row.col.f32.f16.f16.f32 "
        "{%0,%1,%2,%3}, {%4,%5}, {%6}, {%0,%1,%2,%3};"
        : "+f"(d[0]), "+f"(d[1]), "+f"(d[2]), "+f"(d[3])
        : "r"(a[0]), "r"(a[1]), "r"(b0));
}

__global__ void __launch_bounds__(THREADS, 1)
lstm_w16_kernel(const float* __restrict__ x,
                const float* __restrict__ W_ih,
                const float* __restrict__ W_hh,
                const float* __restrict__ b_ih,
                const float* __restrict__ b_hh,
                const float* __restrict__ W_fc,
                const float* __restrict__ b_fc,
                float* __restrict__ out)
{
    extern __shared__ __align__(16) char smc[];
    const u32 sb = (u32)__cvta_generic_to_shared(smc);

    const int tid = threadIdx.x;
    const int w = tid >> 5, l = tid & 31;
    const int mg = w & 7;                   // M-group: 8 gate-k chunks
    const int ng = w >> 3;                  // seq half: 0 -> 0..63, 1 -> 64..127
    const int grp = l >> 3, lr = l & 7;
    const int kml = (mg << 3) + (l >> 2);   // lane's hidden index k

    float* sWfc = (float*)(smc + OFF_WFC);
    float* sBfc = (float*)(smc + OFF_BFC);

    // ---- Stage W (single fp16 plane) in permuted gate-row order ----
    // permuted row p = 32w + 16*tau + tr:
    //   tau=0: tr<8 -> i_{8w+tr}, tr>=8 -> g_{8w+tr-8}
    //   tau=1: tr<8 -> f_{8w+tr}, tr>=8 -> o_{8w+tr-8}
    for (int idx = tid; idx < 256 * 72; idx += THREADS) {
        const int p = idx / 72, col = idx % 72;
        const int pw = p >> 5, tau = (p >> 4) & 1, tr = p & 15;
        const int gate = tau ? ((tr < 8) ? 1 : 3) : ((tr < 8) ? 0 : 2);
        const int orig = (gate << 6) + (pw << 3) + (tr & 7);
        const float v = (col < 64) ? W_hh[orig * 64 + col] : W_ih[orig * 8 + (col - 64)];
        *(u16*)(smc + OFF_WH + p * SROW + col * 2) = fph(v);
    }
    for (int i = tid; i < 512; i += THREADS) sWfc[i] = W_fc[i];
    if (tid < 8) sBfc[tid] = b_fc[tid];

    const float bi = b_ih[kml]       + b_hh[kml];
    const float bf = b_ih[64 + kml]  + b_hh[64 + kml];
    const float bg = b_ih[128 + kml] + b_hh[128 + kml];
    const float bo = b_ih[192 + kml] + b_hh[192 + kml];

    __syncthreads();

    // ---- Static A (weight) fragments (fp16, single plane) ----
    u32 Ah[2][4][4], Ah8[2][2];
    const u32 laneA  = (u32)(((grp & 1) * 8 + lr) * SROW + (grp >> 1) * 16);
    const u32 laneA8 = (u32)((((l >> 3) & 1) * 8 + lr) * SROW + 128);
    #pragma unroll
    for (int tau = 0; tau < 2; tau++) {
        const u32 pr = (u32)(mg * 32 + tau * 16) * SROW;
        #pragma unroll
        for (int kc = 0; kc < 4; kc++)
            ldmx4(Ah[tau][kc], sb + OFF_WH + pr + laneA + kc * 32);
        ldmx2(Ah8[tau], sb + OFF_WH + pr + laneA8);
    }
    __syncthreads();   // done reading W staging; region becomes hx buffers

    // ---- Zero hx buffer 0 h-cols ----
    for (int i = tid; i < 128 * 32; i += THREADS) {
        const int row = i >> 5, cp = i & 31;
        *(u32*)(smc + row * SROW + cp * 4) = 0u;
    }

    // ---- x loader: thread -> (seq = tid/4, channel pair (tid&3)*2) ----
    const int fs = tid >> 2, qc = tid & 3;
    const int gseq = blockIdx.x * TILE + fs;
    const int xb = gseq / Nn, xn = gseq - xb * Nn;
    const float* xp = x + ((size_t)(xb * Tt) * Nn + xn) * 8 + qc * 2;
    const u32 xdst = (u32)(fs * SROW + 128 + qc * 4);
    {   // x_0 -> buffer 0
        const float2 v = *(const float2*)xp;
        *(u32*)(smc + xdst) = (u32)fph(v.x) | ((u32)fph(v.y) << 16);
        xp += Nn * 8;
    }
    __syncthreads();

    const u32 laneB  = (u32)(((grp >> 1) * 8 + lr) * SROW + (grp & 1) * 16);
    const u32 laneB8 = (u32)((((l >> 3) & 1) * 8 + (l & 7)) * SROW + 128);
    const int  sE    = ng * 64 + (l & 3) * 2;   // epilogue base seq for this lane

    // ---- cell state in registers: lane owns (k=kml, 16 fixed seqs) ----
    float cst[16];
    #pragma unroll
    for (int i = 0; i < 16; i++) cst[i] = 0.0f;

    // =================== time loop ===================
    #pragma unroll 1
    for (int t = 0; t < Tt; ++t) {
        const u32 rb  = sb + (u32)(t & 1) * PLANE;          // read buffer
        const u32 wbo = (u32)((t + 1) & 1) * PLANE;         // write buffer offset

        float D[2][2][2][4];    // [pipeline buf][tau][nt][4]

        // ---- pipelined passes: MMA(p) issued before epilogue(p-1) ----
        #pragma unroll
        for (int p = 0; p < 4; p++) {
            const int db = p & 1;
            #pragma unroll
            for (int a = 0; a < 2; a++)
                #pragma unroll
                for (int n = 0; n < 2; n++)
                    #pragma unroll
                    for (int r = 0; r < 4; r++) D[db][a][n][r] = 0.0f;

            const u32 brow = (u32)(ng * 64 + p * 16) * SROW;
            #pragma unroll
            for (int kc = 0; kc < 4; kc++) {
                u32 Bh[4];
                ldmx4(Bh, rb + brow + laneB + (u32)kc * 32);
                #pragma unroll
                for (int tau = 0; tau < 2; tau++) {
                    mma16(D[db][tau][0], Ah[tau][kc], Bh[0], Bh[1]);
                    mma16(D[db][tau][1], Ah[tau][kc], Bh[2], Bh[3]);
                }
            }
            {   // x contribution (cols 64..71)
                u32 BhX[2];
                ldmx2(BhX, rb + brow + laneB8);
                #pragma unroll
                for (int tau = 0; tau < 2; tau++)
                    #pragma unroll
                    for (int nt = 0; nt < 2; nt++)
                        mma8(D[db][tau][nt], Ah8[tau], BhX[nt]);
            }

            // ---- epilogue of previous pass (overlaps with this pass's MMAs) ----
            if (p > 0) {
                const int pe = p - 1, eb = 1 - db;
                #pragma unroll
                for (int nt = 0; nt < 2; nt++) {
                    #pragma unroll
                    for (int par = 0; par < 2; par++) {
                        const int s  = sE + pe * 16 + nt * 8 + par;
                        const int ci = pe * 4 + nt * 2 + par;
                        const float iv = sig_ap(D[eb][0][nt][par] + bi);
                        const float gv = tanh_ap(D[eb][0][nt][2 + par] + bg);
                        const float fv = sig_ap(D[eb][1][nt][par] + bf);
                        const float ov = sig_ap(D[eb][1][nt][2 + par] + bo);
                        const float cn = fmaf(fv, cst[ci], iv * gv);
                        cst[ci] = cn;
                        const float hv = ov * tanh_ap(cn);
                        *(u16*)(smc + wbo + s * SROW + kml * 2) = fph(hv);
                    }
                }
            }
        }
        {   // final epilogue (pass 3, buffer 1)
            #pragma unroll
            for (int nt = 0; nt < 2; nt++) {
                #pragma unroll
                for (int par = 0; par < 2; par++) {
                    const int s  = sE + 3 * 16 + nt * 8 + par;
                    const int ci = 3 * 4 + nt * 2 + par;
                    const float iv = sig_ap(D[1][0][nt][par] + bi);
                    const float gv = tanh_ap(D[1][0][nt][2 + par] + bg);
                    const float fv = sig_ap(D[1][1][nt][par] + bf);
                    const float ov = sig_ap(D[1][1][nt][2 + par] + bo);
                    const float cn = fmaf(fv, cst[ci], iv * gv);
                    cst[ci] = cn;
                    const float hv = ov * tanh_ap(cn);
                    *(u16*)(smc + wbo + s * SROW + kml * 2) = fph(hv);
                }
            }
        }

        if (t < Tt - 1) {   // x_{t+1} -> write buffer
            const float2 v = *(const float2*)xp;
            *(u32*)(smc + wbo + xdst) = (u32)fph(v.x) | ((u32)fph(v.y) << 16);
            xp += Nn * 8;
        }
        __syncthreads();    // h_t + x_{t+1} in write buffer visible to all
    }

    // ---- FC epilogue: final h is in buffer 0 (Tt even) ----
    {
        const int c2 = qc * 2;
        float a0 = sBfc[c2], a1 = sBfc[c2 + 1];
        #pragma unroll 8
        for (int p = 0; p < 32; p++) {
            const u32 hh = *(const u32*)(smc + fs * SROW + p * 4);
            const float v0 = fhf((u16)hh);
            const float v1 = fhf((u16)(hh >> 16));
            a0 = fmaf(v0, sWfc[(c2 + 0) * 64 + 2 * p], fmaf(v1, sWfc[(c2 + 0) * 64 + 2 * p + 1], a0));
            a1 = fmaf(v0, sWfc[(c2 + 1) * 64 + 2 * p], fmaf(v1, sWfc[(c2 + 1) * 64 + 2 * p + 1], a1));
        }
        *(float2*)(out + (size_t)gseq * 8 + c2) = make_float2(a0, a1);
    }
}

extern "C" void kernel_launch(void* const* d_in, const int* in_sizes, int n_in,
                              void* d_out, int out_size) {
    const float* x    = (const float*)d_in[0];
    const float* W_ih = (const float*)d_in[1];
    const float* W_hh = (const float*)d_in[2];
    const float* b_ih = (const float*)d_in[3];
    const float* b_hh = (const float*)d_in[4];
    const float* W_fc = (const float*)d_in[5];
    const float* b_fc = (const float*)d_in[6];
    float* out = (float*)d_out;

    cudaFuncSetAttribute(lstm_w16_kernel,
                         cudaFuncAttributeMaxDynamicSharedMemorySize, SMEM_BYTES);
    lstm_w16_kernel<<<GRID, THREADS, SMEM_BYTES>>>(
        x, W_ih, W_hh, b_ih, b_hh, W_fc, b_fc, out);
}